// round 1
// baseline (speedup 1.0000x reference)
#include <cuda_runtime.h>
#include <math.h>

#define B_ 8
#define C_ 16
#define S_ 512
#define E_ 256
#define BC_ (B_ * C_)

// Scratch for projected Q (pre-scaled), K, V. 3 * 64MB.
__device__ float g_q[(size_t)BC_ * S_ * E_];
__device__ float g_k[(size_t)BC_ * S_ * E_];
__device__ float g_v[(size_t)BC_ * S_ * E_];

// ---------------------------------------------------------------------------
// Projection: Y[bc] = relu(X[bc] @ W[c] + bias[c]) * scale
// Grid: (S/64, E/64, BC), 256 threads. 64x64 tile, 4x4 micro-tile.
// ---------------------------------------------------------------------------
__global__ __launch_bounds__(256) void proj_kernel(
    const float* __restrict__ X, const float* __restrict__ W,
    const float* __restrict__ bias, float* __restrict__ Y, float scale)
{
    __shared__ float As[64][17];   // [m][k] pitch 17 (conflict-safe broadcast reads)
    __shared__ float Ws[16][64];   // [k][n] strided-column reads are conflict-free

    const int bc = blockIdx.z;
    const int c  = bc % C_;
    const float* Xp = X    + (size_t)bc * S_ * E_;
    const float* Wp = W    + (size_t)c  * E_ * E_;
    const float* bp = bias + (size_t)c  * E_;
    float*       Yp = Y    + (size_t)bc * S_ * E_;

    const int m0 = blockIdx.x * 64;
    const int n0 = blockIdx.y * 64;
    const int t  = threadIdx.x;
    const int tx = t & 15;        // column group
    const int ty = t >> 4;        // row group (0..15)

    float acc[4][4] = {};

    for (int k0 = 0; k0 < E_; k0 += 16) {
        // Load A tile 64x16: thread (ty,tx) loads rows ty+16i, k = tx
        #pragma unroll
        for (int i = 0; i < 4; i++)
            As[ty + i * 16][tx] = Xp[(size_t)(m0 + ty + i * 16) * E_ + k0 + tx];
        // Load W tile 16x64: kk = t/64 + 4i, col = t%64 (coalesced)
        #pragma unroll
        for (int i = 0; i < 4; i++)
            Ws[(t >> 6) + i * 4][t & 63] =
                Wp[(size_t)(k0 + (t >> 6) + i * 4) * E_ + n0 + (t & 63)];
        __syncthreads();

        #pragma unroll
        for (int kk = 0; kk < 16; kk++) {
            float a[4], b[4];
            #pragma unroll
            for (int i = 0; i < 4; i++) a[i] = As[ty * 4 + i][kk];
            #pragma unroll
            for (int j = 0; j < 4; j++) b[j] = Ws[kk][tx + 16 * j];
            #pragma unroll
            for (int i = 0; i < 4; i++)
                #pragma unroll
                for (int j = 0; j < 4; j++)
                    acc[i][j] += a[i] * b[j];
        }
        __syncthreads();
    }

    #pragma unroll
    for (int i = 0; i < 4; i++) {
        const int row = m0 + ty * 4 + i;
        #pragma unroll
        for (int j = 0; j < 4; j++) {
            const int col = n0 + tx + 16 * j;
            float v = acc[i][j] + bp[col];
            v = fmaxf(v, 0.0f) * scale;
            Yp[(size_t)row * E_ + col] = v;
        }
    }
}

// ---------------------------------------------------------------------------
// Attention: per (bc, 32-row query tile). Full 32x512 score tile in smem.
// Grid: (S/32, BC), 256 threads, ~160KB dynamic smem.
// ---------------------------------------------------------------------------
#define QP 257   // sQ pitch
#define KP 257   // sK / sV pitch
#define SP 513   // sS pitch

__global__ __launch_bounds__(256) void attn_kernel(float* __restrict__ out)
{
    extern __shared__ float sm[];
    float* sQ = sm;                       // 32 * 257
    float* sK = sQ + 32 * QP;             // 64 * 257  (reused for V)
    float* sS = sK + 64 * KP;             // 32 * 513

    const int bc = blockIdx.y;
    const int q0 = blockIdx.x * 32;
    const float* Q = g_q + (size_t)bc * S_ * E_;
    const float* K = g_k + (size_t)bc * S_ * E_;
    const float* V = g_v + (size_t)bc * S_ * E_;
    float*       O = out + (size_t)bc * S_ * E_;

    const int t  = threadIdx.x;
    const int tx = t & 15;
    const int ty = t >> 4;   // 0..15

    // Load Q tile (32 x 256), coalesced
    for (int idx = t; idx < 32 * E_; idx += 256) {
        const int r = idx >> 8, e = idx & 255;
        sQ[r * QP + e] = Q[(size_t)(q0 + r) * E_ + e];
    }
    __syncthreads();

    // ---- Scores: S = Q K^T  (Q already scaled by E^-0.5) ----
    for (int kt = 0; kt < S_; kt += 64) {
        for (int idx = t; idx < 64 * E_; idx += 256) {
            const int r = idx >> 8, e = idx & 255;
            sK[r * KP + e] = K[(size_t)(kt + r) * E_ + e];
        }
        __syncthreads();

        float acc0[4] = {}, acc1[4] = {};
        const int r0 = ty * 2;
        #pragma unroll 4
        for (int e = 0; e < E_; e++) {
            const float a0 = sQ[r0 * QP + e];
            const float a1 = sQ[(r0 + 1) * QP + e];
            #pragma unroll
            for (int j = 0; j < 4; j++) {
                const float bv = sK[(tx + 16 * j) * KP + e];
                acc0[j] += a0 * bv;
                acc1[j] += a1 * bv;
            }
        }
        #pragma unroll
        for (int j = 0; j < 4; j++) {
            sS[r0 * SP + kt + tx + 16 * j]       = acc0[j];
            sS[(r0 + 1) * SP + kt + tx + 16 * j] = acc1[j];
        }
        __syncthreads();
    }

    // ---- Softmax: warp per row (8 warps x 4 rows) ----
    const int warp = t >> 5, lane = t & 31;
    for (int r = warp * 4; r < warp * 4 + 4; r++) {
        float* row = sS + r * SP;
        float m = -1e30f;
        for (int cidx = lane; cidx < S_; cidx += 32) m = fmaxf(m, row[cidx]);
        #pragma unroll
        for (int o = 16; o > 0; o >>= 1) m = fmaxf(m, __shfl_xor_sync(0xFFFFFFFFu, m, o));
        float s = 0.0f;
        for (int cidx = lane; cidx < S_; cidx += 32) {
            const float ev = __expf(row[cidx] - m);
            row[cidx] = ev;
            s += ev;
        }
        #pragma unroll
        for (int o = 16; o > 0; o >>= 1) s += __shfl_xor_sync(0xFFFFFFFFu, s, o);
        const float inv = 1.0f / s;
        for (int cidx = lane; cidx < S_; cidx += 32) row[cidx] *= inv;
    }
    __syncthreads();

    // ---- Out = P @ V : thread owns 2 rows x 16 strided cols ----
    float o0[16] = {}, o1[16] = {};
    const int r0 = ty * 2;
    for (int kt = 0; kt < S_; kt += 64) {
        for (int idx = t; idx < 64 * E_; idx += 256) {
            const int r = idx >> 8, e = idx & 255;
            sK[r * KP + e] = V[(size_t)(kt + r) * E_ + e];
        }
        __syncthreads();

        for (int kk = 0; kk < 64; kk++) {
            const float p0 = sS[r0 * SP + kt + kk];
            const float p1 = sS[(r0 + 1) * SP + kt + kk];
            #pragma unroll
            for (int j = 0; j < 16; j++) {
                const float vv = sK[kk * KP + tx + 16 * j];
                o0[j] += p0 * vv;
                o1[j] += p1 * vv;
            }
        }
        __syncthreads();
    }

    #pragma unroll
    for (int j = 0; j < 16; j++) {
        O[(size_t)(q0 + r0) * E_ + tx + 16 * j]     = o0[j];
        O[(size_t)(q0 + r0 + 1) * E_ + tx + 16 * j] = o1[j];
    }
}

// ---------------------------------------------------------------------------
extern "C" void kernel_launch(void* const* d_in, const int* in_sizes, int n_in,
                              void* d_out, int out_size)
{
    const float* query = (const float*)d_in[0];
    const float* key   = (const float*)d_in[1];
    const float* value = (const float*)d_in[2];
    const float* wq    = (const float*)d_in[3];
    const float* wk    = (const float*)d_in[4];
    const float* wv    = (const float*)d_in[5];
    const float* bq    = (const float*)d_in[6];
    const float* bk    = (const float*)d_in[7];
    const float* bv    = (const float*)d_in[8];
    float* out = (float*)d_out;

    float *qp, *kp, *vp;
    cudaGetSymbolAddress((void**)&qp, g_q);
    cudaGetSymbolAddress((void**)&kp, g_k);
    cudaGetSymbolAddress((void**)&vp, g_v);

    const float qscale = 1.0f / sqrtf((float)E_);   // 0.0625

    dim3 pgrid(S_ / 64, E_ / 64, BC_);
    proj_kernel<<<pgrid, 256>>>(query, wq, bq, qp, qscale);
    proj_kernel<<<pgrid, 256>>>(key,   wk, bk, kp, 1.0f);
    proj_kernel<<<pgrid, 256>>>(value, wv, bv, vp, 1.0f);

    const size_t smem = (size_t)(32 * QP + 64 * KP + 32 * SP) * sizeof(float);
    cudaFuncSetAttribute(attn_kernel, cudaFuncAttributeMaxDynamicSharedMemorySize,
                         (int)smem);
    attn_kernel<<<dim3(S_ / 32, BC_), 256, smem>>>(out);
}

// round 2
// speedup vs baseline: 1.9425x; 1.9425x over previous
#include <cuda_runtime.h>
#include <math.h>

#define B_ 8
#define C_ 16
#define S_ 512
#define E_ 256
#define BC_ (B_ * C_)

// Scratch for projected Q (pre-scaled), K, V.
__device__ float g_q[(size_t)BC_ * S_ * E_];
__device__ float g_k[(size_t)BC_ * S_ * E_];
__device__ float g_v[(size_t)BC_ * S_ * E_];

// ---------------------------------------------------------------------------
// Projection: Y[bc] = relu(X[bc] @ W[c] + bias[c]) * scale
// (already at fp32 FFMA roofline — unchanged)
// ---------------------------------------------------------------------------
__global__ __launch_bounds__(256) void proj_kernel(
    const float* __restrict__ X, const float* __restrict__ W,
    const float* __restrict__ bias, float* __restrict__ Y, float scale)
{
    __shared__ float As[64][17];
    __shared__ float Ws[16][64];

    const int bc = blockIdx.z;
    const int c  = bc % C_;
    const float* Xp = X    + (size_t)bc * S_ * E_;
    const float* Wp = W    + (size_t)c  * E_ * E_;
    const float* bp = bias + (size_t)c  * E_;
    float*       Yp = Y    + (size_t)bc * S_ * E_;

    const int m0 = blockIdx.x * 64;
    const int n0 = blockIdx.y * 64;
    const int t  = threadIdx.x;
    const int tx = t & 15;
    const int ty = t >> 4;

    float acc[4][4] = {};

    for (int k0 = 0; k0 < E_; k0 += 16) {
        #pragma unroll
        for (int i = 0; i < 4; i++)
            As[ty + i * 16][tx] = Xp[(size_t)(m0 + ty + i * 16) * E_ + k0 + tx];
        #pragma unroll
        for (int i = 0; i < 4; i++)
            Ws[(t >> 6) + i * 4][t & 63] =
                Wp[(size_t)(k0 + (t >> 6) + i * 4) * E_ + n0 + (t & 63)];
        __syncthreads();

        #pragma unroll
        for (int kk = 0; kk < 16; kk++) {
            float a[4], b[4];
            #pragma unroll
            for (int i = 0; i < 4; i++) a[i] = As[ty * 4 + i][kk];
            #pragma unroll
            for (int j = 0; j < 4; j++) b[j] = Ws[kk][tx + 16 * j];
            #pragma unroll
            for (int i = 0; i < 4; i++)
                #pragma unroll
                for (int j = 0; j < 4; j++)
                    acc[i][j] += a[i] * b[j];
        }
        __syncthreads();
    }

    #pragma unroll
    for (int i = 0; i < 4; i++) {
        const int row = m0 + ty * 4 + i;
        #pragma unroll
        for (int j = 0; j < 4; j++) {
            const int col = n0 + tx + 16 * j;
            float v = acc[i][j] + bp[col];
            Yp[(size_t)row * E_ + col] = fmaxf(v, 0.0f) * scale;
        }
    }
}

// ---------------------------------------------------------------------------
// Attention v2: 32 q-rows per CTA; full 32x512 scores in REGISTERS.
// 256 threads: ty = t>>6 (0..3) owns rows 8ty..8ty+7; tx = t&63 owns
// cols tx+64j (j=0..7).  8x8 register micro-tile, float4 smem operands.
// ---------------------------------------------------------------------------
#define EC   16          // e-chunk for score phase
#define QP2  20          // sQ pitch (floats), 16B-aligned rows, conflict-free LDS.128
#define KP2  20          // sK pitch
#define SP2  516         // sS (P matrix) pitch
#define VP2  260         // sV pitch
#define KK_  32          // kk-chunk for PV phase

// smem float offsets
#define OFF_Q   0                      // 32*20   = 640   (also sRed overlay)
#define OFF_K   640                    // 512*20  = 10240
#define OFF_S   (640 + 10240)          // 32*516  = 16512
#define OFF_V   0                      // 32*260  = 8320  (overlays Q/K after phase 1)
#define SMEM_FLOATS (OFF_S + 32 * SP2) // 27392 floats = 109568 B

__global__ __launch_bounds__(256) void attn_kernel(float* __restrict__ out)
{
    extern __shared__ float sm[];
    float* sQ   = sm + OFF_Q;
    float* sK   = sm + OFF_K;
    float* sS   = sm + OFF_S;
    float* sV   = sm + OFF_V;
    float* sRed = sm + OFF_Q;   // 128 floats: [0..63] max partials, [64..127] sums

    const int bc = blockIdx.y;
    const int q0 = blockIdx.x * 32;
    const float* Q = g_q + (size_t)bc * S_ * E_;
    const float* K = g_k + (size_t)bc * S_ * E_;
    const float* V = g_v + (size_t)bc * S_ * E_;
    float*       O = out + (size_t)bc * S_ * E_;

    const int t    = threadIdx.x;
    const int tx   = t & 63;
    const int ty   = t >> 6;          // 0..3
    const int warp = t >> 5;          // 0..7 ; warps 2ty,2ty+1 share row group
    const int lane = t & 31;

    float acc[8][8];
    #pragma unroll
    for (int i = 0; i < 8; i++)
        #pragma unroll
        for (int j = 0; j < 8; j++) acc[i][j] = 0.0f;

    // ================= Phase 1: scores = Q K^T (Q pre-scaled) =============
    for (int ec = 0; ec < E_; ec += EC) {
        __syncthreads();
        // sQ chunk: 32 rows x 16 e  (128 float4, threads 0..127)
        if (t < 128) {
            const int r = t >> 2, e4 = (t & 3) << 2;
            *(float4*)&sQ[r * QP2 + e4] =
                *(const float4*)&Q[(size_t)(q0 + r) * E_ + ec + e4];
        }
        // sK chunk: 512 rows x 16 e (2048 float4, 8 per thread)
        #pragma unroll
        for (int k8 = 0; k8 < 8; k8++) {
            const int idx = t + 256 * k8;
            const int r = idx >> 2, e4 = (idx & 3) << 2;
            *(float4*)&sK[r * KP2 + e4] =
                *(const float4*)&K[(size_t)r * E_ + ec + e4];
        }
        __syncthreads();

        #pragma unroll
        for (int e4 = 0; e4 < EC; e4 += 4) {
            float4 b4[8];
            #pragma unroll
            for (int j = 0; j < 8; j++)
                b4[j] = *(const float4*)&sK[(tx + 64 * j) * KP2 + e4];
            #pragma unroll
            for (int i = 0; i < 8; i++) {
                const float4 a4 = *(const float4*)&sQ[(8 * ty + i) * QP2 + e4];
                #pragma unroll
                for (int j = 0; j < 8; j++) {
                    acc[i][j] += a4.x * b4[j].x;
                    acc[i][j] += a4.y * b4[j].y;
                    acc[i][j] += a4.z * b4[j].z;
                    acc[i][j] += a4.w * b4[j].w;
                }
            }
        }
    }
    __syncthreads();   // phase-1 smem reads done; sRed overlay is now safe

    // ================= Softmax (register scores) ===========================
    float rmax[8];
    #pragma unroll
    for (int i = 0; i < 8; i++) {
        float m = acc[i][0];
        #pragma unroll
        for (int j = 1; j < 8; j++) m = fmaxf(m, acc[i][j]);
        #pragma unroll
        for (int o = 16; o > 0; o >>= 1)
            m = fmaxf(m, __shfl_xor_sync(0xFFFFFFFFu, m, o));
        if (lane == 0) sRed[warp * 8 + i] = m;
        rmax[i] = m;  // placeholder; finalized after combine
    }
    __syncthreads();
    #pragma unroll
    for (int i = 0; i < 8; i++)
        rmax[i] = fmaxf(sRed[warp * 8 + i], sRed[(warp ^ 1) * 8 + i]);

    float rsum[8];
    #pragma unroll
    for (int i = 0; i < 8; i++) {
        float s = 0.0f;
        #pragma unroll
        for (int j = 0; j < 8; j++) {
            const float p = __expf(acc[i][j] - rmax[i]);
            acc[i][j] = p;
            s += p;
        }
        #pragma unroll
        for (int o = 16; o > 0; o >>= 1)
            s += __shfl_xor_sync(0xFFFFFFFFu, s, o);
        if (lane == 0) sRed[64 + warp * 8 + i] = s;
        rsum[i] = s;
    }
    __syncthreads();
    float rinv[8];
    #pragma unroll
    for (int i = 0; i < 8; i++)
        rinv[i] = 1.0f / (sRed[64 + warp * 8 + i] + sRed[64 + (warp ^ 1) * 8 + i]);

    // Store unnormalized P to sS (1/sum folded into epilogue)
    #pragma unroll
    for (int i = 0; i < 8; i++)
        #pragma unroll
        for (int j = 0; j < 8; j++)
            sS[(8 * ty + i) * SP2 + tx + 64 * j] = acc[i][j];

    // ================= Phase 2: out = P V ==================================
    float o_[8][4];
    #pragma unroll
    for (int i = 0; i < 8; i++)
        #pragma unroll
        for (int m = 0; m < 4; m++) o_[i][m] = 0.0f;

    for (int kt = 0; kt < S_; kt += KK_) {
        __syncthreads();  // protects prior sV reads; first iter protects sS writes
        // sV chunk: 32 kk x 256 f (2048 float4, 8 per thread)
        #pragma unroll
        for (int k8 = 0; k8 < 8; k8++) {
            const int idx = t + 256 * k8;
            const int kk = idx >> 6, f4 = (idx & 63) << 2;
            *(float4*)&sV[kk * VP2 + f4] =
                *(const float4*)&V[(size_t)(kt + kk) * E_ + f4];
        }
        __syncthreads();

        #pragma unroll
        for (int kk4 = 0; kk4 < KK_; kk4 += 4) {
            float4 a4[8];
            #pragma unroll
            for (int i = 0; i < 8; i++)
                a4[i] = *(const float4*)&sS[(8 * ty + i) * SP2 + kt + kk4];
            #pragma unroll
            for (int d = 0; d < 4; d++) {
                float b0 = sV[(kk4 + d) * VP2 + tx];
                float b1 = sV[(kk4 + d) * VP2 + tx + 64];
                float b2 = sV[(kk4 + d) * VP2 + tx + 128];
                float b3 = sV[(kk4 + d) * VP2 + tx + 192];
                #pragma unroll
                for (int i = 0; i < 8; i++) {
                    const float av = (d == 0) ? a4[i].x : (d == 1) ? a4[i].y
                                   : (d == 2) ? a4[i].z : a4[i].w;
                    o_[i][0] += av * b0;
                    o_[i][1] += av * b1;
                    o_[i][2] += av * b2;
                    o_[i][3] += av * b3;
                }
            }
        }
    }

    // Epilogue: normalize + store (coalesced: 32 consecutive floats per warp op)
    #pragma unroll
    for (int i = 0; i < 8; i++) {
        const size_t rowoff = (size_t)(q0 + 8 * ty + i) * E_;
        #pragma unroll
        for (int m = 0; m < 4; m++)
            O[rowoff + tx + 64 * m] = o_[i][m] * rinv[i];
    }
    (void)rsum; (void)rmax;
}

// ---------------------------------------------------------------------------
extern "C" void kernel_launch(void* const* d_in, const int* in_sizes, int n_in,
                              void* d_out, int out_size)
{
    const float* query = (const float*)d_in[0];
    const float* key   = (const float*)d_in[1];
    const float* value = (const float*)d_in[2];
    const float* wq    = (const float*)d_in[3];
    const float* wk    = (const float*)d_in[4];
    const float* wv    = (const float*)d_in[5];
    const float* bq    = (const float*)d_in[6];
    const float* bk    = (const float*)d_in[7];
    const float* bv    = (const float*)d_in[8];
    float* out = (float*)d_out;

    float *qp, *kp, *vp;
    cudaGetSymbolAddress((void**)&qp, g_q);
    cudaGetSymbolAddress((void**)&kp, g_k);
    cudaGetSymbolAddress((void**)&vp, g_v);

    const float qscale = 1.0f / sqrtf((float)E_);

    dim3 pgrid(S_ / 64, E_ / 64, BC_);
    proj_kernel<<<pgrid, 256>>>(query, wq, bq, qp, qscale);
    proj_kernel<<<pgrid, 256>>>(key,   wk, bk, kp, 1.0f);
    proj_kernel<<<pgrid, 256>>>(value, wv, bv, vp, 1.0f);

    const size_t smem = (size_t)SMEM_FLOATS * sizeof(float);
    cudaFuncSetAttribute(attn_kernel, cudaFuncAttributeMaxDynamicSharedMemorySize,
                         (int)smem);
    attn_kernel<<<dim3(S_ / 32, BC_), 256, smem>>>(out);
}

// round 4
// speedup vs baseline: 5.4409x; 2.8010x over previous
#include <cuda_runtime.h>
#include <math.h>
#include <stdint.h>

#define B_ 8
#define C_ 16
#define S_ 512
#define E_ 256
#define BC_ (B_ * C_)

// fp32 scratch for projected Q (pre-scaled), K, V.
__device__ float g_q[(size_t)BC_ * S_ * E_];
__device__ float g_k[(size_t)BC_ * S_ * E_];
__device__ float g_v[(size_t)BC_ * S_ * E_];

// ---------------------------------------------------------------------------
// helpers
// ---------------------------------------------------------------------------
__device__ __forceinline__ uint32_t f2tf(float f) {
    uint32_t r;
    asm("cvt.rna.tf32.f32 %0, %1;" : "=r"(r) : "f"(f));
    return r;
}

__device__ __forceinline__ void sts_tf32x4(uint32_t* dst, float4 v) {
    uint4 u;
    u.x = f2tf(v.x); u.y = f2tf(v.y); u.z = f2tf(v.z); u.w = f2tf(v.w);
    *(uint4*)dst = u;
}

// D += A(16x8,row) * B(8x8,col)   tf32 -> fp32
__device__ __forceinline__ void mma8(float* c, const uint32_t* a, const uint32_t* b) {
    asm volatile(
        "mma.sync.aligned.m16n8k8.row.col.f32.tf32.tf32.f32 "
        "{%0,%1,%2,%3}, {%4,%5,%6,%7}, {%8,%9}, {%0,%1,%2,%3};"
        : "+f"(c[0]), "+f"(c[1]), "+f"(c[2]), "+f"(c[3])
        : "r"(a[0]), "r"(a[1]), "r"(a[2]), "r"(a[3]), "r"(b[0]), "r"(b[1]));
}

// ---------------------------------------------------------------------------
// Projection: Y[bc] = relu(X[bc] @ W[c] + bias[c]) * scale   (tf32 mma)
// CTA 128x128, 8 warps (2m x 4n), warp tile 64x32, k-chunk 32.
// Grid: (S/128, E/128, BC), 256 threads.
// ---------------------------------------------------------------------------
#define PA 36    // sA pitch (words), 36 % 32 == 4  -> A-frag conflict-free
#define PB 136   // sB pitch (words), 136 % 32 == 8 -> B-frag conflict-free

__global__ __launch_bounds__(256) void proj_kernel(
    const float* __restrict__ X, const float* __restrict__ W,
    const float* __restrict__ bias, float* __restrict__ Y, float scale)
{
    __shared__ uint32_t sA[128 * PA];   // 18.4 KB
    __shared__ uint32_t sB[32 * PB];    // 17.4 KB

    const int bc = blockIdx.z;
    const int c  = bc % C_;
    const float* Xp = X    + (size_t)bc * S_ * E_;
    const float* Wp = W    + (size_t)c  * E_ * E_;
    const float* bp = bias + (size_t)c  * E_;
    float*       Yp = Y    + (size_t)bc * S_ * E_;

    const int m0 = blockIdx.x * 128;
    const int n0 = blockIdx.y * 128;
    const int t  = threadIdx.x;
    const int warp  = t >> 5;
    const int warpm = warp >> 2;   // 0..1
    const int warpn = warp & 3;    // 0..3
    const int lane  = t & 31;
    const int g = lane >> 2;       // 0..7
    const int q = lane & 3;        // 0..3

    float acc[4][4][4];
    #pragma unroll
    for (int i = 0; i < 4; i++)
        #pragma unroll
        for (int j = 0; j < 4; j++)
            #pragma unroll
            for (int r = 0; r < 4; r++) acc[i][j][r] = 0.0f;

    for (int k0 = 0; k0 < E_; k0 += 32) {
        // A tile 128x32 (4 float4 per thread)
        #pragma unroll
        for (int i = 0; i < 4; i++) {
            const int idx = t + 256 * i;
            const int row = idx >> 3, col = (idx & 7) << 2;
            sts_tf32x4(&sA[row * PA + col],
                       *(const float4*)&Xp[(size_t)(m0 + row) * E_ + k0 + col]);
        }
        // B tile 32x128 (4 float4 per thread)
        #pragma unroll
        for (int i = 0; i < 4; i++) {
            const int idx = t + 256 * i;
            const int row = idx >> 5, col = (idx & 31) << 2;
            sts_tf32x4(&sB[row * PB + col],
                       *(const float4*)&Wp[(size_t)(k0 + row) * E_ + n0 + col]);
        }
        __syncthreads();

        #pragma unroll
        for (int kk = 0; kk < 32; kk += 8) {
            uint32_t a[4][4], b[4][2];
            #pragma unroll
            for (int mt = 0; mt < 4; mt++) {
                const int row = warpm * 64 + mt * 16 + g;
                a[mt][0] = sA[row * PA + kk + q];
                a[mt][1] = sA[(row + 8) * PA + kk + q];
                a[mt][2] = sA[row * PA + kk + q + 4];
                a[mt][3] = sA[(row + 8) * PA + kk + q + 4];
            }
            #pragma unroll
            for (int nt = 0; nt < 4; nt++) {
                const int n = warpn * 32 + nt * 8 + g;
                b[nt][0] = sB[(kk + q) * PB + n];
                b[nt][1] = sB[(kk + q + 4) * PB + n];
            }
            #pragma unroll
            for (int mt = 0; mt < 4; mt++)
                #pragma unroll
                for (int nt = 0; nt < 4; nt++)
                    mma8(acc[mt][nt], a[mt], b[nt]);
        }
        __syncthreads();
    }

    // Epilogue: bias + relu + scale
    #pragma unroll
    for (int nt = 0; nt < 4; nt++) {
        const int col = n0 + warpn * 32 + nt * 8 + 2 * q;
        const float bias0 = bp[col], bias1 = bp[col + 1];
        #pragma unroll
        for (int mt = 0; mt < 4; mt++) {
            const int row = m0 + warpm * 64 + mt * 16 + g;
            float2 v0, v1;
            v0.x = fmaxf(acc[mt][nt][0] + bias0, 0.0f) * scale;
            v0.y = fmaxf(acc[mt][nt][1] + bias1, 0.0f) * scale;
            v1.x = fmaxf(acc[mt][nt][2] + bias0, 0.0f) * scale;
            v1.y = fmaxf(acc[mt][nt][3] + bias1, 0.0f) * scale;
            *(float2*)&Yp[(size_t)row * E_ + col]       = v0;
            *(float2*)&Yp[(size_t)(row + 8) * E_ + col] = v1;
        }
    }
}

// ---------------------------------------------------------------------------
// Attention (tf32 mma): 32 q-rows per CTA, full 32x512 scores in registers.
// 8 warps; warp owns 64 score cols (8 n-tiles), 2 m-tiles (32 rows).
// Phase2: warp owns 32 out cols (4 n-tiles).
// ---------------------------------------------------------------------------
#define PQ  36     // sQ pitch (A-frag, %32==4)
#define PK  36     // sK pitch (B-frag via n*PK+q pattern -> 4g+q, ok)
#define SP3 516    // sS pitch (A-frag, 516%32==4)
#define PV  264    // sV pitch (B-frag, 264%32==8)

#define OFF_S3   0                          // 32*516  = 16512 u32
#define OFF_V3   16512                      // 32*264  = 8448
#define OFF_Q3   0                          // phase1 overlay: 32*36 = 1152
#define OFF_K3   1152                       // 512*36 = 18432 (ends 19584)
#define OFF_RED  24960                      // 512 floats (max: 256, sum: 256)
#define ATT_WORDS (OFF_RED + 512)           // 25472 u32 = 101888 B

__global__ __launch_bounds__(256) void attn_kernel(float* __restrict__ out)
{
    extern __shared__ uint32_t smu[];
    uint32_t* sS = smu + OFF_S3;
    uint32_t* sV = smu + OFF_V3;
    uint32_t* sQ = smu + OFF_Q3;
    uint32_t* sK = smu + OFF_K3;
    float* sRedM = (float*)(smu + OFF_RED);        // [32 rows][8 warps]
    float* sRedS = (float*)(smu + OFF_RED + 256);

    const int bc = blockIdx.y;
    const int q0 = blockIdx.x * 32;
    const float* Q = g_q + (size_t)bc * S_ * E_;
    const float* K = g_k + (size_t)bc * S_ * E_;
    const float* V = g_v + (size_t)bc * S_ * E_;
    float*       O = out + (size_t)bc * S_ * E_;

    const int t    = threadIdx.x;
    const int warp = t >> 5;
    const int lane = t & 31;
    const int g = lane >> 2;
    const int q = lane & 3;

    // ---------------- Phase 1: scores = Q K^T (Q pre-scaled) --------------
    float acc[2][8][4];
    #pragma unroll
    for (int mt = 0; mt < 2; mt++)
        #pragma unroll
        for (int nt = 0; nt < 8; nt++)
            #pragma unroll
            for (int r = 0; r < 4; r++) acc[mt][nt][r] = 0.0f;

    for (int ec = 0; ec < E_; ec += 32) {
        __syncthreads();
        // sQ: 32x32 (1 float4/thread)
        {
            const int row = t >> 3, col = (t & 7) << 2;
            sts_tf32x4(&sQ[row * PQ + col],
                       *(const float4*)&Q[(size_t)(q0 + row) * E_ + ec + col]);
        }
        // sK: 512x32 (16 float4/thread)
        #pragma unroll
        for (int i = 0; i < 16; i++) {
            const int idx = t + 256 * i;
            const int row = idx >> 3, col = (idx & 7) << 2;
            sts_tf32x4(&sK[row * PK + col],
                       *(const float4*)&K[(size_t)row * E_ + ec + col]);
        }
        __syncthreads();

        #pragma unroll
        for (int kk = 0; kk < 32; kk += 8) {
            uint32_t a[2][4], b[8][2];
            #pragma unroll
            for (int mt = 0; mt < 2; mt++) {
                const int row = mt * 16 + g;
                a[mt][0] = sQ[row * PQ + kk + q];
                a[mt][1] = sQ[(row + 8) * PQ + kk + q];
                a[mt][2] = sQ[row * PQ + kk + q + 4];
                a[mt][3] = sQ[(row + 8) * PQ + kk + q + 4];
            }
            #pragma unroll
            for (int nt = 0; nt < 8; nt++) {
                const int n = warp * 64 + nt * 8 + g;   // K row (score col)
                b[nt][0] = sK[n * PK + kk + q];
                b[nt][1] = sK[n * PK + kk + q + 4];
            }
            #pragma unroll
            for (int mt = 0; mt < 2; mt++)
                #pragma unroll
                for (int nt = 0; nt < 8; nt++)
                    mma8(acc[mt][nt], a[mt], b[nt]);
        }
    }

    // ---------------- Softmax on register fragments ------------------------
    // slot s = mt*2+h owns row (mt*16 + h*8 + g); 16 values per slot.
    float rmax[4], rinv[4];
    #pragma unroll
    for (int mt = 0; mt < 2; mt++)
        #pragma unroll
        for (int h = 0; h < 2; h++) {
            float m = -1e30f;
            #pragma unroll
            for (int nt = 0; nt < 8; nt++) {
                m = fmaxf(m, acc[mt][nt][2 * h]);
                m = fmaxf(m, acc[mt][nt][2 * h + 1]);
            }
            m = fmaxf(m, __shfl_xor_sync(0xFFFFFFFFu, m, 1));
            m = fmaxf(m, __shfl_xor_sync(0xFFFFFFFFu, m, 2));
            rmax[mt * 2 + h] = m;
        }
    __syncthreads();            // all phase-1 smem reads done (sS overlay safe)
    if (q == 0) {
        #pragma unroll
        for (int mt = 0; mt < 2; mt++)
            #pragma unroll
            for (int h = 0; h < 2; h++)
                sRedM[(mt * 16 + h * 8 + g) * 8 + warp] = rmax[mt * 2 + h];
    }
    __syncthreads();
    #pragma unroll
    for (int s = 0; s < 4; s++) {
        const int row = (s >> 1) * 16 + (s & 1) * 8 + g;
        float m = sRedM[row * 8];
        #pragma unroll
        for (int w = 1; w < 8; w++) m = fmaxf(m, sRedM[row * 8 + w]);
        rmax[s] = m;
    }

    float rsum[4];
    #pragma unroll
    for (int mt = 0; mt < 2; mt++)
        #pragma unroll
        for (int h = 0; h < 2; h++) {
            float s = 0.0f;
            #pragma unroll
            for (int nt = 0; nt < 8; nt++) {
                float p0 = __expf(acc[mt][nt][2 * h]     - rmax[mt * 2 + h]);
                float p1 = __expf(acc[mt][nt][2 * h + 1] - rmax[mt * 2 + h]);
                acc[mt][nt][2 * h]     = p0;
                acc[mt][nt][2 * h + 1] = p1;
                s += p0 + p1;
            }
            s += __shfl_xor_sync(0xFFFFFFFFu, s, 1);
            s += __shfl_xor_sync(0xFFFFFFFFu, s, 2);
            rsum[mt * 2 + h] = s;
        }
    if (q == 0) {
        #pragma unroll
        for (int mt = 0; mt < 2; mt++)
            #pragma unroll
            for (int h = 0; h < 2; h++)
                sRedS[(mt * 16 + h * 8 + g) * 8 + warp] = rsum[mt * 2 + h];
    }
    __syncthreads();
    #pragma unroll
    for (int s = 0; s < 4; s++) {
        const int row = (s >> 1) * 16 + (s & 1) * 8 + g;
        float sum = 0.0f;
        #pragma unroll
        for (int w = 0; w < 8; w++) sum += sRedS[row * 8 + w];
        rinv[s] = 1.0f / sum;
    }

    // Store unnormalized P (tf32) to sS
    #pragma unroll
    for (int mt = 0; mt < 2; mt++)
        #pragma unroll
        for (int h = 0; h < 2; h++) {
            const int row = mt * 16 + h * 8 + g;
            #pragma unroll
            for (int nt = 0; nt < 8; nt++) {
                const int col = warp * 64 + nt * 8 + 2 * q;
                uint2 u;
                u.x = f2tf(acc[mt][nt][2 * h]);
                u.y = f2tf(acc[mt][nt][2 * h + 1]);
                *(uint2*)&sS[row * SP3 + col] = u;
            }
        }

    // ---------------- Phase 2: out = P V ----------------------------------
    float acc2[2][4][4];
    #pragma unroll
    for (int mt = 0; mt < 2; mt++)
        #pragma unroll
        for (int nt = 0; nt < 4; nt++)
            #pragma unroll
            for (int r = 0; r < 4; r++) acc2[mt][nt][r] = 0.0f;

    for (int kt = 0; kt < S_; kt += 32) {
        __syncthreads();
        // sV: 32x256 (8 float4/thread)
        #pragma unroll
        for (int i = 0; i < 8; i++) {
            const int idx = t + 256 * i;
            const int row = idx >> 6, col = (idx & 63) << 2;
            sts_tf32x4(&sV[row * PV + col],
                       *(const float4*)&V[(size_t)(kt + row) * E_ + col]);
        }
        __syncthreads();

        #pragma unroll
        for (int kk = 0; kk < 32; kk += 8) {
            uint32_t a[2][4], b[4][2];
            #pragma unroll
            for (int mt = 0; mt < 2; mt++) {
                const int row = mt * 16 + g;
                a[mt][0] = sS[row * SP3 + kt + kk + q];
                a[mt][1] = sS[(row + 8) * SP3 + kt + kk + q];
                a[mt][2] = sS[row * SP3 + kt + kk + q + 4];
                a[mt][3] = sS[(row + 8) * SP3 + kt + kk + q + 4];
            }
            #pragma unroll
            for (int nt = 0; nt < 4; nt++) {
                const int n = warp * 32 + nt * 8 + g;
                b[nt][0] = sV[(kk + q) * PV + n];
                b[nt][1] = sV[(kk + q + 4) * PV + n];
            }
            #pragma unroll
            for (int mt = 0; mt < 2; mt++)
                #pragma unroll
                for (int nt = 0; nt < 4; nt++)
                    mma8(acc2[mt][nt], a[mt], b[nt]);
        }
    }

    // Epilogue: normalize + store
    #pragma unroll
    for (int mt = 0; mt < 2; mt++)
        #pragma unroll
        for (int h = 0; h < 2; h++) {
            const int row = q0 + mt * 16 + h * 8 + g;
            const float inv = rinv[mt * 2 + h];
            #pragma unroll
            for (int nt = 0; nt < 4; nt++) {
                const int col = warp * 32 + nt * 8 + 2 * q;
                float2 v;
                v.x = acc2[mt][nt][2 * h]     * inv;
                v.y = acc2[mt][nt][2 * h + 1] * inv;
                *(float2*)&O[(size_t)row * E_ + col] = v;
            }
        }
}

// ---------------------------------------------------------------------------
extern "C" void kernel_launch(void* const* d_in, const int* in_sizes, int n_in,
                              void* d_out, int out_size)
{
    const float* query = (const float*)d_in[0];
    const float* key   = (const float*)d_in[1];
    const float* value = (const float*)d_in[2];
    const float* wq    = (const float*)d_in[3];
    const float* wk    = (const float*)d_in[4];
    const float* wv    = (const float*)d_in[5];
    const float* bq    = (const float*)d_in[6];
    const float* bk    = (const float*)d_in[7];
    const float* bv    = (const float*)d_in[8];
    float* out = (float*)d_out;

    float *qp, *kp, *vp;
    cudaGetSymbolAddress((void**)&qp, g_q);
    cudaGetSymbolAddress((void**)&kp, g_k);
    cudaGetSymbolAddress((void**)&vp, g_v);

    const float qscale = 1.0f / sqrtf((float)E_);

    dim3 pgrid(S_ / 128, E_ / 128, BC_);
    proj_kernel<<<pgrid, 256>>>(query, wq, bq, qp, qscale);
    proj_kernel<<<pgrid, 256>>>(key,   wk, bk, kp, 1.0f);
    proj_kernel<<<pgrid, 256>>>(value, wv, bv, vp, 1.0f);

    const size_t smem = (size_t)ATT_WORDS * sizeof(uint32_t);
    cudaFuncSetAttribute(attn_kernel, cudaFuncAttributeMaxDynamicSharedMemorySize,
                         (int)smem);
    attn_kernel<<<dim3(S_ / 32, BC_), 256, smem>>>(out);
}

// round 6
// speedup vs baseline: 7.1469x; 1.3136x over previous
#include <cuda_runtime.h>
#include <math.h>
#include <stdint.h>

#define B_ 8
#define C_ 16
#define S_ 512
#define E_ 256
#define BC_ (B_ * C_)

// fp32 scratch for projected Q (pre-scaled), K, V.
__device__ float g_q[(size_t)BC_ * S_ * E_];
__device__ float g_k[(size_t)BC_ * S_ * E_];
__device__ float g_v[(size_t)BC_ * S_ * E_];

// ---------------------------------------------------------------------------
// helpers
// ---------------------------------------------------------------------------
// pack (lo, hi) floats -> bf16x2 word (lo in bits[0:16)).
__device__ __forceinline__ uint32_t pk2(float lo, float hi) {
    uint32_t r;
    asm("cvt.rn.bf16x2.f32 %0, %1, %2;" : "=r"(r) : "f"(hi), "f"(lo));
    return r;
}
// float4 (4 consecutive elems) -> 2 packed words
__device__ __forceinline__ uint2 pk4(float4 v) {
    uint2 u;
    u.x = pk2(v.x, v.y);
    u.y = pk2(v.z, v.w);
    return u;
}

// D += A(16x16,row) * B(16x8,col)   bf16 -> fp32
__device__ __forceinline__ void mma16(float* c, const uint32_t* a, const uint32_t* b) {
    asm volatile(
        "mma.sync.aligned.m16n8k16.row.col.f32.bf16.bf16.f32 "
        "{%0,%1,%2,%3}, {%4,%5,%6,%7}, {%8,%9}, {%0,%1,%2,%3};"
        : "+f"(c[0]), "+f"(c[1]), "+f"(c[2]), "+f"(c[3])
        : "r"(a[0]), "r"(a[1]), "r"(a[2]), "r"(a[3]), "r"(b[0]), "r"(b[1]));
}

// ---------------------------------------------------------------------------
// Projection (merged q/k/v): Y[bc] = relu(X[bc] @ W[c] + bias[c]) * scale
// CTA 128x128, 8 warps (2m x 4n), warp tile 64x32, k-chunk 64 elems (32 pairs).
// Grid: (S/128, E/128, 3*BC), 256 threads.
// A in smem: [row][kpair]  pitch PA  (A-frag banks: 4g+q, conflict-free)
// B in smem: [kpair][n]    pitch PBP (B-frag banks: 8q+g, conflict-free)
// ---------------------------------------------------------------------------
#define PA  36    // 36 % 32 == 4
#define PBP 136   // 136 % 32 == 8

__global__ __launch_bounds__(256) void proj_kernel(
    const float* __restrict__ query, const float* __restrict__ key,
    const float* __restrict__ value,
    const float* __restrict__ wq, const float* __restrict__ wk,
    const float* __restrict__ wv,
    const float* __restrict__ bq, const float* __restrict__ bk,
    const float* __restrict__ bv, float qscale)
{
    __shared__ uint32_t sA[128 * PA];   // 18.4 KB
    __shared__ uint32_t sB[32 * PBP];   // 17.4 KB

    const int zi    = blockIdx.z;
    const int which = zi >> 7;          // zi / BC_  (BC_=128)
    const int bc    = zi & (BC_ - 1);
    const int c     = bc % C_;

    const float *X, *W, *bp;
    float* Yp;
    float scale;
    if (which == 0)      { X = query; W = wq; bp = bq; Yp = g_q; scale = qscale; }
    else if (which == 1) { X = key;   W = wk; bp = bk; Yp = g_k; scale = 1.0f; }
    else                 { X = value; W = wv; bp = bv; Yp = g_v; scale = 1.0f; }
    X  += (size_t)bc * S_ * E_;
    W  += (size_t)c  * E_ * E_;
    bp += (size_t)c  * E_;
    Yp += (size_t)bc * S_ * E_;

    const int m0 = blockIdx.x * 128;
    const int n0 = blockIdx.y * 128;
    const int t  = threadIdx.x;
    const int warp  = t >> 5;
    const int warpm = warp >> 2;
    const int warpn = warp & 3;
    const int lane  = t & 31;
    const int g = lane >> 2;
    const int q = lane & 3;

    float acc[4][4][4];
    #pragma unroll
    for (int i = 0; i < 4; i++)
        #pragma unroll
        for (int j = 0; j < 4; j++)
            #pragma unroll
            for (int r = 0; r < 4; r++) acc[i][j][r] = 0.0f;

    for (int k0 = 0; k0 < E_; k0 += 64) {
        // A tile 128x64 elems: 2048 float4, 8 per thread
        #pragma unroll
        for (int i = 0; i < 8; i++) {
            const int idx = t + 256 * i;
            const int row = idx >> 4, c4 = idx & 15;
            *(uint2*)&sA[row * PA + c4 * 2] =
                pk4(*(const float4*)&X[(size_t)(m0 + row) * E_ + k0 + 4 * c4]);
        }
        // B tile 64x128 elems as [kpair][n]: pairs span two W rows
        #pragma unroll
        for (int i = 0; i < 4; i++) {
            const int idx = t + 256 * i;
            const int kp = idx >> 5, n4 = (idx & 31) * 4;
            const float4 w0 = *(const float4*)&W[(size_t)(k0 + 2 * kp)     * E_ + n0 + n4];
            const float4 w1 = *(const float4*)&W[(size_t)(k0 + 2 * kp + 1) * E_ + n0 + n4];
            uint4 u;
            u.x = pk2(w0.x, w1.x); u.y = pk2(w0.y, w1.y);
            u.z = pk2(w0.z, w1.z); u.w = pk2(w0.w, w1.w);
            *(uint4*)&sB[kp * PBP + n4] = u;
        }
        __syncthreads();

        #pragma unroll
        for (int kkp = 0; kkp < 32; kkp += 8) {   // 4 mma k-steps of K=16
            uint32_t a[4][4], b[4][2];
            #pragma unroll
            for (int mt = 0; mt < 4; mt++) {
                const int row = warpm * 64 + mt * 16 + g;
                a[mt][0] = sA[row * PA + kkp + q];
                a[mt][1] = sA[(row + 8) * PA + kkp + q];
                a[mt][2] = sA[row * PA + kkp + q + 4];
                a[mt][3] = sA[(row + 8) * PA + kkp + q + 4];
            }
            #pragma unroll
            for (int nt = 0; nt < 4; nt++) {
                const int n = warpn * 32 + nt * 8 + g;
                b[nt][0] = sB[(kkp + q) * PBP + n];
                b[nt][1] = sB[(kkp + q + 4) * PBP + n];
            }
            #pragma unroll
            for (int mt = 0; mt < 4; mt++)
                #pragma unroll
                for (int nt = 0; nt < 4; nt++)
                    mma16(acc[mt][nt], a[mt], b[nt]);
        }
        __syncthreads();
    }

    // Epilogue: bias + relu + scale
    #pragma unroll
    for (int nt = 0; nt < 4; nt++) {
        const int col = n0 + warpn * 32 + nt * 8 + 2 * q;
        const float bias0 = bp[col], bias1 = bp[col + 1];
        #pragma unroll
        for (int mt = 0; mt < 4; mt++) {
            const int row = m0 + warpm * 64 + mt * 16 + g;
            float2 v0, v1;
            v0.x = fmaxf(acc[mt][nt][0] + bias0, 0.0f) * scale;
            v0.y = fmaxf(acc[mt][nt][1] + bias1, 0.0f) * scale;
            v1.x = fmaxf(acc[mt][nt][2] + bias0, 0.0f) * scale;
            v1.y = fmaxf(acc[mt][nt][3] + bias1, 0.0f) * scale;
            *(float2*)&Yp[(size_t)row * E_ + col]       = v0;
            *(float2*)&Yp[(size_t)(row + 8) * E_ + col] = v1;
        }
    }
}

// ---------------------------------------------------------------------------
// Attention (bf16 mma): 32 q-rows/CTA, full 32x512 scores in registers.
// Phase1: warp owns 64 score cols (8 n-tiles), 2 m-tiles. e-chunk 64.
// Phase2: warp owns 32 out cols (4 n-tiles). s-chunk 32.
// ---------------------------------------------------------------------------
#define PQ   36    // sQ pitch  (A-frag: 4g+q)
#define PK4  36    // sK pitch  (B-frag via n*PK4: 4g+q)
#define SP4  260   // sS pitch  (A-frag: 4g+q; 260%32==4)
#define PV4  264   // sV pitch  (B-frag: 8q+g; 264%32==8)

#define OFF_S4   0                       // 32*260 = 8320 words
#define OFF_V4   8448                    // 16*264 = 4224 -> ends 12672
#define OFF_Q4   0                       // phase1 overlay: 32*36 = 1152
#define OFF_K4   1152                    // 512*36 = 18432 -> ends 19584
#define OFF_RED4 19584                   // 512 floats
#define ATT_WORDS (OFF_RED4 + 512)       // 20096 words = 80384 B

__global__ __launch_bounds__(256) void attn_kernel(float* __restrict__ out)
{
    extern __shared__ uint32_t smu[];
    uint32_t* sS = smu + OFF_S4;
    uint32_t* sV = smu + OFF_V4;
    uint32_t* sQ = smu + OFF_Q4;
    uint32_t* sK = smu + OFF_K4;
    float* sRedM = (float*)(smu + OFF_RED4);       // [32 rows][8 warps]
    float* sRedS = (float*)(smu + OFF_RED4 + 256);

    const int bc = blockIdx.y;
    const int q0 = blockIdx.x * 32;
    const float* Q = g_q + (size_t)bc * S_ * E_;
    const float* K = g_k + (size_t)bc * S_ * E_;
    const float* V = g_v + (size_t)bc * S_ * E_;
    float*       O = out + (size_t)bc * S_ * E_;

    const int t    = threadIdx.x;
    const int warp = t >> 5;
    const int lane = t & 31;
    const int g = lane >> 2;
    const int q = lane & 3;

    // ---------------- Phase 1: scores = Q K^T (Q pre-scaled) --------------
    float acc[2][8][4];
    #pragma unroll
    for (int mt = 0; mt < 2; mt++)
        #pragma unroll
        for (int nt = 0; nt < 8; nt++)
            #pragma unroll
            for (int r = 0; r < 4; r++) acc[mt][nt][r] = 0.0f;

    for (int ec = 0; ec < E_; ec += 64) {
        __syncthreads();
        // sQ: 32x64 elems (512 float4, 2/thread)
        #pragma unroll
        for (int i = 0; i < 2; i++) {
            const int idx = t + 256 * i;
            const int row = idx >> 4, c4 = idx & 15;
            *(uint2*)&sQ[row * PQ + c4 * 2] =
                pk4(*(const float4*)&Q[(size_t)(q0 + row) * E_ + ec + 4 * c4]);
        }
        // sK: 512x64 elems (8192 float4, 32/thread)
        #pragma unroll 8
        for (int i = 0; i < 32; i++) {
            const int idx = t + 256 * i;
            const int row = idx >> 4, c4 = idx & 15;
            *(uint2*)&sK[row * PK4 + c4 * 2] =
                pk4(*(const float4*)&K[(size_t)row * E_ + ec + 4 * c4]);
        }
        __syncthreads();

        #pragma unroll
        for (int kkp = 0; kkp < 32; kkp += 8) {
            uint32_t a[2][4], b[8][2];
            #pragma unroll
            for (int mt = 0; mt < 2; mt++) {
                const int row = mt * 16 + g;
                a[mt][0] = sQ[row * PQ + kkp + q];
                a[mt][1] = sQ[(row + 8) * PQ + kkp + q];
                a[mt][2] = sQ[row * PQ + kkp + q + 4];
                a[mt][3] = sQ[(row + 8) * PQ + kkp + q + 4];
            }
            #pragma unroll
            for (int nt = 0; nt < 8; nt++) {
                const int n = warp * 64 + nt * 8 + g;   // key row (score col)
                b[nt][0] = sK[n * PK4 + kkp + q];
                b[nt][1] = sK[n * PK4 + kkp + q + 4];
            }
            #pragma unroll
            for (int mt = 0; mt < 2; mt++)
                #pragma unroll
                for (int nt = 0; nt < 8; nt++)
                    mma16(acc[mt][nt], a[mt], b[nt]);
        }
    }

    // ---------------- Softmax on register fragments (fp32) -----------------
    float rmax[4], rinv[4];
    #pragma unroll
    for (int mt = 0; mt < 2; mt++)
        #pragma unroll
        for (int h = 0; h < 2; h++) {
            float m = -1e30f;
            #pragma unroll
            for (int nt = 0; nt < 8; nt++) {
                m = fmaxf(m, acc[mt][nt][2 * h]);
                m = fmaxf(m, acc[mt][nt][2 * h + 1]);
            }
            m = fmaxf(m, __shfl_xor_sync(0xFFFFFFFFu, m, 1));
            m = fmaxf(m, __shfl_xor_sync(0xFFFFFFFFu, m, 2));
            rmax[mt * 2 + h] = m;
        }
    __syncthreads();              // all phase-1 smem reads done
    if (q == 0) {
        #pragma unroll
        for (int mt = 0; mt < 2; mt++)
            #pragma unroll
            for (int h = 0; h < 2; h++)
                sRedM[(mt * 16 + h * 8 + g) * 8 + warp] = rmax[mt * 2 + h];
    }
    __syncthreads();
    #pragma unroll
    for (int s = 0; s < 4; s++) {
        const int row = (s >> 1) * 16 + (s & 1) * 8 + g;
        float m = sRedM[row * 8];
        #pragma unroll
        for (int w = 1; w < 8; w++) m = fmaxf(m, sRedM[row * 8 + w]);
        rmax[s] = m;
    }

    #pragma unroll
    for (int mt = 0; mt < 2; mt++)
        #pragma unroll
        for (int h = 0; h < 2; h++) {
            float s = 0.0f;
            #pragma unroll
            for (int nt = 0; nt < 8; nt++) {
                float p0 = __expf(acc[mt][nt][2 * h]     - rmax[mt * 2 + h]);
                float p1 = __expf(acc[mt][nt][2 * h + 1] - rmax[mt * 2 + h]);
                acc[mt][nt][2 * h]     = p0;
                acc[mt][nt][2 * h + 1] = p1;
                s += p0 + p1;
            }
            s += __shfl_xor_sync(0xFFFFFFFFu, s, 1);
            s += __shfl_xor_sync(0xFFFFFFFFu, s, 2);
            if (q == 0) sRedS[(mt * 16 + h * 8 + g) * 8 + warp] = s;
        }
    __syncthreads();
    #pragma unroll
    for (int s = 0; s < 4; s++) {
        const int row = (s >> 1) * 16 + (s & 1) * 8 + g;
        float sum = 0.0f;
        #pragma unroll
        for (int w = 0; w < 8; w++) sum += sRedS[row * 8 + w];
        rinv[s] = 1.0f / sum;
    }

    // Store unnormalized P (bf16 pairs) to sS — overlays sQ/sK (phase1 done)
    #pragma unroll
    for (int mt = 0; mt < 2; mt++)
        #pragma unroll
        for (int h = 0; h < 2; h++) {
            const int row = mt * 16 + h * 8 + g;
            #pragma unroll
            for (int nt = 0; nt < 8; nt++)
                sS[row * SP4 + warp * 32 + nt * 4 + q] =
                    pk2(acc[mt][nt][2 * h], acc[mt][nt][2 * h + 1]);
        }

    // ---------------- Phase 2: out = P V ----------------------------------
    float acc2[2][4][4];
    #pragma unroll
    for (int mt = 0; mt < 2; mt++)
        #pragma unroll
        for (int nt = 0; nt < 4; nt++)
            #pragma unroll
            for (int r = 0; r < 4; r++) acc2[mt][nt][r] = 0.0f;

    for (int kt = 0; kt < S_; kt += 32) {
        __syncthreads();
        // sV: 32 s-rows x 256 f as [kpair][n] (pairs span two V rows)
        #pragma unroll
        for (int i = 0; i < 4; i++) {
            const int idx = t + 256 * i;
            const int kp = idx >> 6, n4 = (idx & 63) * 4;
            const float4 v0 = *(const float4*)&V[(size_t)(kt + 2 * kp)     * E_ + n4];
            const float4 v1 = *(const float4*)&V[(size_t)(kt + 2 * kp + 1) * E_ + n4];
            uint4 u;
            u.x = pk2(v0.x, v1.x); u.y = pk2(v0.y, v1.y);
            u.z = pk2(v0.z, v1.z); u.w = pk2(v0.w, v1.w);
            *(uint4*)&sV[kp * PV4 + n4] = u;
        }
        __syncthreads();   // also makes all warps' P stores visible (1st iter)

        const int ktp = kt >> 1;
        #pragma unroll
        for (int kkp = 0; kkp < 16; kkp += 8) {
            uint32_t a[2][4], b[4][2];
            #pragma unroll
            for (int mt = 0; mt < 2; mt++) {
                const int row = mt * 16 + g;
                a[mt][0] = sS[row * SP4 + ktp + kkp + q];
                a[mt][1] = sS[(row + 8) * SP4 + ktp + kkp + q];
                a[mt][2] = sS[row * SP4 + ktp + kkp + q + 4];
                a[mt][3] = sS[(row + 8) * SP4 + ktp + kkp + q + 4];
            }
            #pragma unroll
            for (int nt = 0; nt < 4; nt++) {
                const int n = warp * 32 + nt * 8 + g;
                b[nt][0] = sV[(kkp + q) * PV4 + n];
                b[nt][1] = sV[(kkp + q + 4) * PV4 + n];
            }
            #pragma unroll
            for (int mt = 0; mt < 2; mt++)
                #pragma unroll
                for (int nt = 0; nt < 4; nt++)
                    mma16(acc2[mt][nt], a[mt], b[nt]);
        }
    }

    // Epilogue: normalize + store
    #pragma unroll
    for (int mt = 0; mt < 2; mt++)
        #pragma unroll
        for (int h = 0; h < 2; h++) {
            const int row = q0 + mt * 16 + h * 8 + g;
            const float inv = rinv[mt * 2 + h];
            #pragma unroll
            for (int nt = 0; nt < 4; nt++) {
                const int col = warp * 32 + nt * 8 + 2 * q;
                float2 v;
                v.x = acc2[mt][nt][2 * h]     * inv;
                v.y = acc2[mt][nt][2 * h + 1] * inv;
                *(float2*)&O[(size_t)row * E_ + col] = v;
            }
        }
}

// ---------------------------------------------------------------------------
extern "C" void kernel_launch(void* const* d_in, const int* in_sizes, int n_in,
                              void* d_out, int out_size)
{
    const float* query = (const float*)d_in[0];
    const float* key   = (const float*)d_in[1];
    const float* value = (const float*)d_in[2];
    const float* wq    = (const float*)d_in[3];
    const float* wk    = (const float*)d_in[4];
    const float* wv    = (const float*)d_in[5];
    const float* bq    = (const float*)d_in[6];
    const float* bk    = (const float*)d_in[7];
    const float* bv    = (const float*)d_in[8];
    float* out = (float*)d_out;

    const float qscale = 1.0f / sqrtf((float)E_);

    dim3 pgrid(S_ / 128, E_ / 128, 3 * BC_);
    proj_kernel<<<pgrid, 256>>>(query, key, value, wq, wk, wv, bq, bk, bv, qscale);

    const size_t smem = (size_t)ATT_WORDS * sizeof(uint32_t);
    cudaFuncSetAttribute(attn_kernel, cudaFuncAttributeMaxDynamicSharedMemorySize,
                         (int)smem);
    attn_kernel<<<dim3(S_ / 32, BC_), 256, smem>>>(out);
}

// round 7
// speedup vs baseline: 11.5100x; 1.6105x over previous
#include <cuda_runtime.h>
#include <math.h>
#include <stdint.h>

#define B_ 8
#define C_ 16
#define S_ 512
#define E_ 256
#define BC_ 128
#define EW  128   // bf16x2 words per row (E/2)

// bf16 scratch: q/k as [s][e-pair]; v pre-paired along s: [sp][e]
__device__ uint32_t g_q[(size_t)BC_ * S_ * EW];
__device__ uint32_t g_k[(size_t)BC_ * S_ * EW];
__device__ uint32_t g_v[(size_t)BC_ * (S_ / 2) * E_];

// ---------------------------------------------------------------------------
// helpers
// ---------------------------------------------------------------------------
__device__ __forceinline__ uint32_t pk2(float lo, float hi) {
    uint32_t r;
    asm("cvt.rn.bf16x2.f32 %0, %1, %2;" : "=r"(r) : "f"(hi), "f"(lo));
    return r;
}
__device__ __forceinline__ uint2 pk4(float4 v) {
    uint2 u; u.x = pk2(v.x, v.y); u.y = pk2(v.z, v.w); return u;
}
__device__ __forceinline__ void mma16(float* c, const uint32_t* a, const uint32_t* b) {
    asm volatile(
        "mma.sync.aligned.m16n8k16.row.col.f32.bf16.bf16.f32 "
        "{%0,%1,%2,%3}, {%4,%5,%6,%7}, {%8,%9}, {%0,%1,%2,%3};"
        : "+f"(c[0]), "+f"(c[1]), "+f"(c[2]), "+f"(c[3])
        : "r"(a[0]), "r"(a[1]), "r"(a[2]), "r"(a[3]), "r"(b[0]), "r"(b[1]));
}
__device__ __forceinline__ void cpa16(uint32_t smem_addr, const void* gptr) {
    asm volatile("cp.async.cg.shared.global [%0], [%1], 16;"
                 :: "r"(smem_addr), "l"(gptr));
}
#define CP_COMMIT() asm volatile("cp.async.commit_group;")
#define CP_WAIT0()  asm volatile("cp.async.wait_group 0;")

// ---------------------------------------------------------------------------
// Projection (merged q/k/v): Y[bc] = relu(X[bc] @ W[c] + bias[c]) * scale
// CTA 128x128, 8 warps (2m x 4n), k-chunk 64 elems. Outputs bf16 scratch.
// ---------------------------------------------------------------------------
#define PA  36
#define PBP 136

__global__ __launch_bounds__(256) void proj_kernel(
    const float* __restrict__ query, const float* __restrict__ key,
    const float* __restrict__ value,
    const float* __restrict__ wq, const float* __restrict__ wk,
    const float* __restrict__ wv,
    const float* __restrict__ bq, const float* __restrict__ bk,
    const float* __restrict__ bv, float qscale)
{
    __shared__ uint32_t sA[128 * PA];
    __shared__ uint32_t sB[32 * PBP];

    const int zi    = blockIdx.z;
    const int which = zi >> 7;
    const int bc    = zi & (BC_ - 1);
    const int c     = bc % C_;

    const float *X, *W, *bp;
    uint32_t* Yw;
    float scale;
    if (which == 0)      { X = query; W = wq; bp = bq; Yw = g_q + (size_t)bc * S_ * EW; scale = qscale; }
    else if (which == 1) { X = key;   W = wk; bp = bk; Yw = g_k + (size_t)bc * S_ * EW; scale = 1.0f; }
    else                 { X = value; W = wv; bp = bv; Yw = g_v + (size_t)bc * (S_/2) * E_; scale = 1.0f; }
    X  += (size_t)bc * S_ * E_;
    W  += (size_t)c  * E_ * E_;
    bp += (size_t)c  * E_;

    const int m0 = blockIdx.x * 128;
    const int n0 = blockIdx.y * 128;
    const int t  = threadIdx.x;
    const int warp  = t >> 5;
    const int warpm = warp >> 2;
    const int warpn = warp & 3;
    const int lane  = t & 31;
    const int g = lane >> 2;
    const int q = lane & 3;

    float acc[4][4][4];
    #pragma unroll
    for (int i = 0; i < 4; i++)
        #pragma unroll
        for (int j = 0; j < 4; j++)
            #pragma unroll
            for (int r = 0; r < 4; r++) acc[i][j][r] = 0.0f;

    for (int k0 = 0; k0 < E_; k0 += 64) {
        #pragma unroll
        for (int i = 0; i < 8; i++) {
            const int idx = t + 256 * i;
            const int row = idx >> 4, c4 = idx & 15;
            *(uint2*)&sA[row * PA + c4 * 2] =
                pk4(*(const float4*)&X[(size_t)(m0 + row) * E_ + k0 + 4 * c4]);
        }
        #pragma unroll
        for (int i = 0; i < 4; i++) {
            const int idx = t + 256 * i;
            const int kp = idx >> 5, n4 = (idx & 31) * 4;
            const float4 w0 = *(const float4*)&W[(size_t)(k0 + 2 * kp)     * E_ + n0 + n4];
            const float4 w1 = *(const float4*)&W[(size_t)(k0 + 2 * kp + 1) * E_ + n0 + n4];
            uint4 u;
            u.x = pk2(w0.x, w1.x); u.y = pk2(w0.y, w1.y);
            u.z = pk2(w0.z, w1.z); u.w = pk2(w0.w, w1.w);
            *(uint4*)&sB[kp * PBP + n4] = u;
        }
        __syncthreads();

        #pragma unroll
        for (int kkp = 0; kkp < 32; kkp += 8) {
            uint32_t a[4][4], b[4][2];
            #pragma unroll
            for (int mt = 0; mt < 4; mt++) {
                const int row = warpm * 64 + mt * 16 + g;
                a[mt][0] = sA[row * PA + kkp + q];
                a[mt][1] = sA[(row + 8) * PA + kkp + q];
                a[mt][2] = sA[row * PA + kkp + q + 4];
                a[mt][3] = sA[(row + 8) * PA + kkp + q + 4];
            }
            #pragma unroll
            for (int nt = 0; nt < 4; nt++) {
                const int n = warpn * 32 + nt * 8 + g;
                b[nt][0] = sB[(kkp + q) * PBP + n];
                b[nt][1] = sB[(kkp + q + 4) * PBP + n];
            }
            #pragma unroll
            for (int mt = 0; mt < 4; mt++)
                #pragma unroll
                for (int nt = 0; nt < 4; nt++)
                    mma16(acc[mt][nt], a[mt], b[nt]);
        }
        __syncthreads();
    }

    // Epilogue: bias + relu + scale -> bf16 scratch
    #pragma unroll
    for (int nt = 0; nt < 4; nt++) {
        const int col = n0 + warpn * 32 + nt * 8 + 2 * q;
        const float b0v = bp[col], b1v = bp[col + 1];
        #pragma unroll
        for (int mt = 0; mt < 4; mt++) {
            const int row = m0 + warpm * 64 + mt * 16 + g;
            const float v00 = fmaxf(acc[mt][nt][0] + b0v, 0.0f) * scale;
            const float v01 = fmaxf(acc[mt][nt][1] + b1v, 0.0f) * scale;
            const float v10 = fmaxf(acc[mt][nt][2] + b0v, 0.0f) * scale;
            const float v11 = fmaxf(acc[mt][nt][3] + b1v, 0.0f) * scale;
            if (which != 2) {
                const int cw = (n0 >> 1) + warpn * 16 + nt * 4 + q;
                Yw[(size_t)row * EW + cw]       = pk2(v00, v01);
                Yw[(size_t)(row + 8) * EW + cw] = pk2(v10, v11);
            } else {
                // pair adjacent s-rows (row even with row+1) across lanes g, g^1
                const float p00 = __shfl_xor_sync(0xFFFFFFFFu, v00, 4);
                const float p01 = __shfl_xor_sync(0xFFFFFFFFu, v01, 4);
                const float p10 = __shfl_xor_sync(0xFFFFFFFFu, v10, 4);
                const float p11 = __shfl_xor_sync(0xFFFFFFFFu, v11, 4);
                if ((g & 1) == 0) {
                    const int sp0 = row >> 1;   // row is even here
                    uint2 u0, u1;
                    u0.x = pk2(v00, p00); u0.y = pk2(v01, p01);
                    u1.x = pk2(v10, p10); u1.y = pk2(v11, p11);
                    *(uint2*)&Yw[(size_t)sp0 * E_ + col]       = u0;
                    *(uint2*)&Yw[(size_t)(sp0 + 4) * E_ + col] = u1;
                }
            }
        }
    }
}

// ---------------------------------------------------------------------------
// Attention: 32 q-rows/CTA, scores in registers, cp.async double-buffering.
// Phase1: 8 e-chunks of 32 elems (16 words). Phase2: 8 kt-chunks of 64 s.
// ---------------------------------------------------------------------------
#define PQF 132   // sQ pitch  (%32==4)
#define PKC 20    // sK chunk pitch (banks 4*perm(g)+q)
#define SPP 260   // sS pitch  (%32==4)
#define PVC 264   // sV pitch  (%32==8)

#define OFF_SQ  0            // 32*132  = 4224
#define OFF_K0  4224         // 512*20  = 10240
#define OFF_K1  14464        // ends 24704
#define OFF_SS  0            // 32*260  = 8320 (overlay)
#define OFF_V0  8320         // 32*264  = 8448
#define OFF_V1  16768        // ends 25216
#define OFF_RD  25216        // 512 floats
#define ATT_WORDS 25728      // 102912 B

__global__ __launch_bounds__(256, 2) void attn_kernel(float* __restrict__ out)
{
    extern __shared__ uint32_t smu[];
    uint32_t* sQ = smu + OFF_SQ;
    uint32_t* sS = smu + OFF_SS;
    float* sRedM = (float*)(smu + OFF_RD);
    float* sRedS = (float*)(smu + OFF_RD + 256);

    const uint32_t smb = (uint32_t)__cvta_generic_to_shared(smu);
    const uint32_t bK[2] = { smb + OFF_K0 * 4u, smb + OFF_K1 * 4u };
    const uint32_t bV[2] = { smb + OFF_V0 * 4u, smb + OFF_V1 * 4u };

    const int bc = blockIdx.y;
    const int q0 = blockIdx.x * 32;
    const uint32_t* Qw = g_q + (size_t)bc * S_ * EW;
    const uint32_t* Kw = g_k + (size_t)bc * S_ * EW;
    const uint32_t* Vw = g_v + (size_t)bc * (S_ / 2) * E_;
    float*          O  = out + (size_t)bc * S_ * E_;

    const int t    = threadIdx.x;
    const int warp = t >> 5;
    const int lane = t & 31;
    const int g = lane >> 2;
    const int q = lane & 3;

    // ---- stage whole Q tile (32 x 128 words) ------------------------------
    #pragma unroll
    for (int i = 0; i < 4; i++) {
        const int o = t + 256 * i;
        const int row = o >> 5, j = o & 31;
        *(uint4*)&sQ[row * PQF + j * 4] =
            *(const uint4*)&Qw[(size_t)(q0 + row) * EW + j * 4];
    }

    // ---- issue K chunk 0 --------------------------------------------------
    {
        #pragma unroll
        for (int i = 0; i < 8; i++) {
            const int o = t + 256 * i;
            const int s = o >> 2, jj = o & 3;
            cpa16(bK[0] + (uint32_t)(s * PKC + jj * 4) * 4u,
                  Kw + (size_t)s * EW + jj * 4);
        }
        CP_COMMIT();
    }

    // ---------------- Phase 1: scores = Q K^T ------------------------------
    float acc[2][8][4];
    #pragma unroll
    for (int mt = 0; mt < 2; mt++)
        #pragma unroll
        for (int nt = 0; nt < 8; nt++)
            #pragma unroll
            for (int r = 0; r < 4; r++) acc[mt][nt][r] = 0.0f;

    #pragma unroll 1
    for (int cch = 0; cch < 8; cch++) {
        CP_WAIT0();
        __syncthreads();
        if (cch < 7) {
            const uint32_t dst = bK[(cch + 1) & 1];
            const int ecp = (cch + 1) * 16;
            #pragma unroll
            for (int i = 0; i < 8; i++) {
                const int o = t + 256 * i;
                const int s = o >> 2, jj = o & 3;
                cpa16(dst + (uint32_t)(s * PKC + jj * 4) * 4u,
                      Kw + (size_t)s * EW + ecp + jj * 4);
            }
            CP_COMMIT();
        }
        const uint32_t* bufK = smu + ((cch & 1) ? OFF_K1 : OFF_K0);
        const int ecp = cch * 16;
        #pragma unroll
        for (int kkp = 0; kkp < 16; kkp += 8) {
            uint32_t a[2][4], b[8][2];
            #pragma unroll
            for (int mt = 0; mt < 2; mt++) {
                const int row = mt * 16 + g;
                a[mt][0] = sQ[row * PQF + ecp + kkp + q];
                a[mt][1] = sQ[(row + 8) * PQF + ecp + kkp + q];
                a[mt][2] = sQ[row * PQF + ecp + kkp + q + 4];
                a[mt][3] = sQ[(row + 8) * PQF + ecp + kkp + q + 4];
            }
            #pragma unroll
            for (int nt = 0; nt < 8; nt++) {
                const int n = warp * 64 + nt * 8 + g;
                b[nt][0] = bufK[n * PKC + kkp + q];
                b[nt][1] = bufK[n * PKC + kkp + q + 4];
            }
            #pragma unroll
            for (int mt = 0; mt < 2; mt++)
                #pragma unroll
                for (int nt = 0; nt < 8; nt++)
                    mma16(acc[mt][nt], a[mt], b[nt]);
        }
    }

    // ---------------- Softmax (fp32 on fragments) --------------------------
    float rmax[4], rinv[4];
    #pragma unroll
    for (int mt = 0; mt < 2; mt++)
        #pragma unroll
        for (int h = 0; h < 2; h++) {
            float m = -1e30f;
            #pragma unroll
            for (int nt = 0; nt < 8; nt++) {
                m = fmaxf(m, acc[mt][nt][2 * h]);
                m = fmaxf(m, acc[mt][nt][2 * h + 1]);
            }
            m = fmaxf(m, __shfl_xor_sync(0xFFFFFFFFu, m, 1));
            m = fmaxf(m, __shfl_xor_sync(0xFFFFFFFFu, m, 2));
            rmax[mt * 2 + h] = m;
        }
    __syncthreads();   // all phase-1 smem reads done

    // issue V chunk 0 (overlaps the whole softmax)
    {
        #pragma unroll
        for (int i = 0; i < 8; i++) {
            const int o = t + 256 * i;
            const int spl = o >> 6, jj = o & 63;
            cpa16(bV[0] + (uint32_t)(spl * PVC + jj * 4) * 4u,
                  Vw + (size_t)spl * E_ + jj * 4);
        }
        CP_COMMIT();
    }

    if (q == 0) {
        #pragma unroll
        for (int mt = 0; mt < 2; mt++)
            #pragma unroll
            for (int h = 0; h < 2; h++)
                sRedM[(mt * 16 + h * 8 + g) * 8 + warp] = rmax[mt * 2 + h];
    }
    __syncthreads();
    #pragma unroll
    for (int s = 0; s < 4; s++) {
        const int row = (s >> 1) * 16 + (s & 1) * 8 + g;
        float m = sRedM[row * 8];
        #pragma unroll
        for (int w = 1; w < 8; w++) m = fmaxf(m, sRedM[row * 8 + w]);
        rmax[s] = m;
    }

    #pragma unroll
    for (int mt = 0; mt < 2; mt++)
        #pragma unroll
        for (int h = 0; h < 2; h++) {
            float s = 0.0f;
            #pragma unroll
            for (int nt = 0; nt < 8; nt++) {
                float p0 = __expf(acc[mt][nt][2 * h]     - rmax[mt * 2 + h]);
                float p1 = __expf(acc[mt][nt][2 * h + 1] - rmax[mt * 2 + h]);
                acc[mt][nt][2 * h]     = p0;
                acc[mt][nt][2 * h + 1] = p1;
                s += p0 + p1;
            }
            s += __shfl_xor_sync(0xFFFFFFFFu, s, 1);
            s += __shfl_xor_sync(0xFFFFFFFFu, s, 2);
            if (q == 0) sRedS[(mt * 16 + h * 8 + g) * 8 + warp] = s;
        }
    __syncthreads();
    #pragma unroll
    for (int s = 0; s < 4; s++) {
        const int row = (s >> 1) * 16 + (s & 1) * 8 + g;
        float sum = 0.0f;
        #pragma unroll
        for (int w = 0; w < 8; w++) sum += sRedS[row * 8 + w];
        rinv[s] = 1.0f / sum;
    }

    // Store unnormalized P (bf16 pairs) to sS
    #pragma unroll
    for (int mt = 0; mt < 2; mt++)
        #pragma unroll
        for (int h = 0; h < 2; h++) {
            const int row = mt * 16 + h * 8 + g;
            #pragma unroll
            for (int nt = 0; nt < 8; nt++)
                sS[row * SPP + warp * 32 + nt * 4 + q] =
                    pk2(acc[mt][nt][2 * h], acc[mt][nt][2 * h + 1]);
        }

    // ---------------- Phase 2: out = P V -----------------------------------
    float acc2[2][4][4];
    #pragma unroll
    for (int mt = 0; mt < 2; mt++)
        #pragma unroll
        for (int nt = 0; nt < 4; nt++)
            #pragma unroll
            for (int r = 0; r < 4; r++) acc2[mt][nt][r] = 0.0f;

    #pragma unroll 1
    for (int cch = 0; cch < 8; cch++) {
        CP_WAIT0();
        __syncthreads();           // V chunk ready + (first iter) P visible
        if (cch < 7) {
            const uint32_t dst = bV[(cch + 1) & 1];
            const int base_sp = (cch + 1) * 32;
            #pragma unroll
            for (int i = 0; i < 8; i++) {
                const int o = t + 256 * i;
                const int spl = o >> 6, jj = o & 63;
                cpa16(dst + (uint32_t)(spl * PVC + jj * 4) * 4u,
                      Vw + (size_t)(base_sp + spl) * E_ + jj * 4);
            }
            CP_COMMIT();
        }
        const uint32_t* bufV = smu + ((cch & 1) ? OFF_V1 : OFF_V0);
        const int ktp = cch * 32;
        #pragma unroll
        for (int kkp = 0; kkp < 32; kkp += 8) {
            uint32_t a[2][4], b[4][2];
            #pragma unroll
            for (int mt = 0; mt < 2; mt++) {
                const int row = mt * 16 + g;
                a[mt][0] = sS[row * SPP + ktp + kkp + q];
                a[mt][1] = sS[(row + 8) * SPP + ktp + kkp + q];
                a[mt][2] = sS[row * SPP + ktp + kkp + q + 4];
                a[mt][3] = sS[(row + 8) * SPP + ktp + kkp + q + 4];
            }
            #pragma unroll
            for (int nt = 0; nt < 4; nt++) {
                const int n = warp * 32 + nt * 8 + g;
                b[nt][0] = bufV[(kkp + q) * PVC + n];
                b[nt][1] = bufV[(kkp + q + 4) * PVC + n];
            }
            #pragma unroll
            for (int mt = 0; mt < 2; mt++)
                #pragma unroll
                for (int nt = 0; nt < 4; nt++)
                    mma16(acc2[mt][nt], a[mt], b[nt]);
        }
    }

    // Epilogue: normalize + store fp32
    #pragma unroll
    for (int mt = 0; mt < 2; mt++)
        #pragma unroll
        for (int h = 0; h < 2; h++) {
            const int row = q0 + mt * 16 + h * 8 + g;
            const float inv = rinv[mt * 2 + h];
            #pragma unroll
            for (int nt = 0; nt < 4; nt++) {
                const int col = warp * 32 + nt * 8 + 2 * q;
                float2 v;
                v.x = acc2[mt][nt][2 * h]     * inv;
                v.y = acc2[mt][nt][2 * h + 1] * inv;
                *(float2*)&O[(size_t)row * E_ + col] = v;
            }
        }
}

// ---------------------------------------------------------------------------
extern "C" void kernel_launch(void* const* d_in, const int* in_sizes, int n_in,
                              void* d_out, int out_size)
{
    const float* query = (const float*)d_in[0];
    const float* key   = (const float*)d_in[1];
    const float* value = (const float*)d_in[2];
    const float* wq    = (const float*)d_in[3];
    const float* wk    = (const float*)d_in[4];
    const float* wv    = (const float*)d_in[5];
    const float* bq    = (const float*)d_in[6];
    const float* bk    = (const float*)d_in[7];
    const float* bv    = (const float*)d_in[8];
    float* out = (float*)d_out;

    const float qscale = 1.0f / sqrtf((float)E_);

    dim3 pgrid(S_ / 128, E_ / 128, 3 * BC_);
    proj_kernel<<<pgrid, 256>>>(query, key, value, wq, wk, wv, bq, bk, bv, qscale);

    const size_t smem = (size_t)ATT_WORDS * sizeof(uint32_t);
    cudaFuncSetAttribute(attn_kernel, cudaFuncAttributeMaxDynamicSharedMemorySize,
                         (int)smem);
    attn_kernel<<<dim3(S_ / 32, BC_), 256, smem>>>(out);
}

// round 8
// speedup vs baseline: 11.7414x; 1.0201x over previous
#include <cuda_runtime.h>
#include <math.h>
#include <stdint.h>

#define B_ 8
#define C_ 16
#define S_ 512
#define E_ 256
#define BC_ 128
#define EW  128   // bf16x2 words per row (E/2)
#define SP_ 256   // s-pairs (S/2)

// bf16 scratch: q/k as [s][e-pair]; v TRANSPOSED: [f][s-pair]
__device__ uint32_t g_q[(size_t)BC_ * S_ * EW];
__device__ uint32_t g_k[(size_t)BC_ * S_ * EW];
__device__ uint32_t g_v[(size_t)BC_ * E_ * SP_];

// ---------------------------------------------------------------------------
// helpers
// ---------------------------------------------------------------------------
__device__ __forceinline__ uint32_t pk2(float lo, float hi) {
    uint32_t r;
    asm("cvt.rn.bf16x2.f32 %0, %1, %2;" : "=r"(r) : "f"(hi), "f"(lo));
    return r;
}
__device__ __forceinline__ uint2 pk4(float4 v) {
    uint2 u; u.x = pk2(v.x, v.y); u.y = pk2(v.z, v.w); return u;
}
__device__ __forceinline__ void mma16(float* c, const uint32_t* a, const uint32_t* b) {
    asm volatile(
        "mma.sync.aligned.m16n8k16.row.col.f32.bf16.bf16.f32 "
        "{%0,%1,%2,%3}, {%4,%5,%6,%7}, {%8,%9}, {%0,%1,%2,%3};"
        : "+f"(c[0]), "+f"(c[1]), "+f"(c[2]), "+f"(c[3])
        : "r"(a[0]), "r"(a[1]), "r"(a[2]), "r"(a[3]), "r"(b[0]), "r"(b[1]));
}
__device__ __forceinline__ void ldsm4(uint32_t* r, uint32_t addr) {
    asm volatile("ldmatrix.sync.aligned.m8n8.x4.shared.b16 {%0,%1,%2,%3}, [%4];"
                 : "=r"(r[0]), "=r"(r[1]), "=r"(r[2]), "=r"(r[3]) : "r"(addr));
}
__device__ __forceinline__ void cpa16(uint32_t smem_addr, const void* gptr) {
    asm volatile("cp.async.cg.shared.global [%0], [%1], 16;"
                 :: "r"(smem_addr), "l"(gptr));
}
#define CP_COMMIT() asm volatile("cp.async.commit_group;")
#define CP_WAIT0()  asm volatile("cp.async.wait_group 0;")

// ---------------------------------------------------------------------------
// Projection (merged q/k/v). CTA 128x128, 8 warps (2m x 4n), k-chunk 64.
// A-frags via ldmatrix. V output written TRANSPOSED via smem staging.
// ---------------------------------------------------------------------------
#define PA  36
#define PBP 136
#define PT  68      // transpose buffer pitch

__global__ __launch_bounds__(256) void proj_kernel(
    const float* __restrict__ query, const float* __restrict__ key,
    const float* __restrict__ value,
    const float* __restrict__ wq, const float* __restrict__ wk,
    const float* __restrict__ wv,
    const float* __restrict__ bq, const float* __restrict__ bk,
    const float* __restrict__ bv, float qscale)
{
    __shared__ uint32_t pool[8960];      // sA(4608) + sB(4352); sT(8704) overlay
    uint32_t* sA = pool;
    uint32_t* sB = pool + 4608;
    uint32_t* sT = pool;

    const int zi    = blockIdx.z;
    const int which = zi >> 7;
    const int bc    = zi & (BC_ - 1);
    const int c     = bc % C_;

    const float *X, *W, *bp;
    uint32_t* Yw;
    float scale;
    if (which == 0)      { X = query; W = wq; bp = bq; Yw = g_q + (size_t)bc * S_ * EW; scale = qscale; }
    else if (which == 1) { X = key;   W = wk; bp = bk; Yw = g_k + (size_t)bc * S_ * EW; scale = 1.0f; }
    else                 { X = value; W = wv; bp = bv; Yw = g_v + (size_t)bc * E_ * SP_; scale = 1.0f; }
    X  += (size_t)bc * S_ * E_;
    W  += (size_t)c  * E_ * E_;
    bp += (size_t)c  * E_;

    const int m0 = blockIdx.x * 128;
    const int n0 = blockIdx.y * 128;
    const int t  = threadIdx.x;
    const int warp  = t >> 5;
    const int warpm = warp >> 2;
    const int warpn = warp & 3;
    const int lane  = t & 31;
    const int g = lane >> 2;
    const int q = lane & 3;

    // ldmatrix A-pattern lane offsets
    const int arow  = (lane & 7) + (((lane >> 3) & 1) << 3);
    const int akadd = (lane >> 4) << 2;
    const uint32_t smbA = (uint32_t)__cvta_generic_to_shared(sA);
    const uint32_t aBase = smbA + (uint32_t)(arow * PA + akadd) * 4u;

    float acc[4][4][4];
    #pragma unroll
    for (int i = 0; i < 4; i++)
        #pragma unroll
        for (int j = 0; j < 4; j++)
            #pragma unroll
            for (int r = 0; r < 4; r++) acc[i][j][r] = 0.0f;

    for (int k0 = 0; k0 < E_; k0 += 64) {
        #pragma unroll
        for (int i = 0; i < 8; i++) {
            const int idx = t + 256 * i;
            const int row = idx >> 4, c4 = idx & 15;
            *(uint2*)&sA[row * PA + c4 * 2] =
                pk4(*(const float4*)&X[(size_t)(m0 + row) * E_ + k0 + 4 * c4]);
        }
        #pragma unroll
        for (int i = 0; i < 4; i++) {
            const int idx = t + 256 * i;
            const int kp = idx >> 5, n4 = (idx & 31) * 4;
            const float4 w0 = *(const float4*)&W[(size_t)(k0 + 2 * kp)     * E_ + n0 + n4];
            const float4 w1 = *(const float4*)&W[(size_t)(k0 + 2 * kp + 1) * E_ + n0 + n4];
            uint4 u;
            u.x = pk2(w0.x, w1.x); u.y = pk2(w0.y, w1.y);
            u.z = pk2(w0.z, w1.z); u.w = pk2(w0.w, w1.w);
            *(uint4*)&sB[kp * PBP + n4] = u;
        }
        __syncthreads();

        #pragma unroll
        for (int kkp = 0; kkp < 32; kkp += 8) {
            uint32_t a[4][4], b[4][2];
            #pragma unroll
            for (int mt = 0; mt < 4; mt++)
                ldsm4(a[mt], aBase + (uint32_t)((warpm * 64 + mt * 16) * PA + kkp) * 4u);
            #pragma unroll
            for (int nt = 0; nt < 4; nt++) {
                const int n = warpn * 32 + nt * 8 + g;
                b[nt][0] = sB[(kkp + q) * PBP + n];
                b[nt][1] = sB[(kkp + q + 4) * PBP + n];
            }
            #pragma unroll
            for (int mt = 0; mt < 4; mt++)
                #pragma unroll
                for (int nt = 0; nt < 4; nt++)
                    mma16(acc[mt][nt], a[mt], b[nt]);
        }
        __syncthreads();
    }

    // Epilogue
    if (which != 2) {
        #pragma unroll
        for (int nt = 0; nt < 4; nt++) {
            const int col = n0 + warpn * 32 + nt * 8 + 2 * q;
            const float b0v = bp[col], b1v = bp[col + 1];
            #pragma unroll
            for (int mt = 0; mt < 4; mt++) {
                const int row = m0 + warpm * 64 + mt * 16 + g;
                const float v00 = fmaxf(acc[mt][nt][0] + b0v, 0.0f) * scale;
                const float v01 = fmaxf(acc[mt][nt][1] + b1v, 0.0f) * scale;
                const float v10 = fmaxf(acc[mt][nt][2] + b0v, 0.0f) * scale;
                const float v11 = fmaxf(acc[mt][nt][3] + b1v, 0.0f) * scale;
                const int cw = (n0 >> 1) + warpn * 16 + nt * 4 + q;
                Yw[(size_t)row * EW + cw]       = pk2(v00, v01);
                Yw[(size_t)(row + 8) * EW + cw] = pk2(v10, v11);
            }
        }
    } else {
        // stage V^T pairs into sT[localcol][localsp], then coalesced write
        #pragma unroll
        for (int nt = 0; nt < 4; nt++) {
            const int col = n0 + warpn * 32 + nt * 8 + 2 * q;
            const float b0v = bp[col], b1v = bp[col + 1];
            #pragma unroll
            for (int mt = 0; mt < 4; mt++) {
                const float v00 = fmaxf(acc[mt][nt][0] + b0v, 0.0f);
                const float v01 = fmaxf(acc[mt][nt][1] + b1v, 0.0f);
                const float v10 = fmaxf(acc[mt][nt][2] + b0v, 0.0f);
                const float v11 = fmaxf(acc[mt][nt][3] + b1v, 0.0f);
                const float p00 = __shfl_xor_sync(0xFFFFFFFFu, v00, 4);
                const float p01 = __shfl_xor_sync(0xFFFFFFFFu, v01, 4);
                const float p10 = __shfl_xor_sync(0xFFFFFFFFu, v10, 4);
                const float p11 = __shfl_xor_sync(0xFFFFFFFFu, v11, 4);
                if ((g & 1) == 0) {
                    const int lcol = warpn * 32 + nt * 8 + 2 * q;
                    const int lsp  = (warpm * 64 + mt * 16 + g) >> 1;
                    sT[lcol * PT + lsp]           = pk2(v00, p00);
                    sT[(lcol + 1) * PT + lsp]     = pk2(v01, p01);
                    sT[lcol * PT + lsp + 4]       = pk2(v10, p10);
                    sT[(lcol + 1) * PT + lsp + 4] = pk2(v11, p11);
                }
            }
        }
        __syncthreads();
        const int spb = m0 >> 1;
        #pragma unroll
        for (int i = 0; i < 8; i++) {
            const int o = t + 256 * i;
            const int col = o >> 4, j = o & 15;
            *(uint4*)&Yw[(size_t)(n0 + col) * SP_ + spb + j * 4] =
                *(uint4*)&sT[col * PT + j * 4];
        }
    }
}

// ---------------------------------------------------------------------------
// Attention: 32 q-rows/CTA, scores in registers, cp.async double-buffering,
// all mma operands via ldmatrix.
// ---------------------------------------------------------------------------
#define PQF 132   // sQ pitch
#define PKC 20    // sK chunk pitch
#define SPP 260   // sS pitch
#define PVT 36    // sV chunk pitch ([f][sp])

#define OFF_SQ  0            // 32*132  = 4224
#define OFF_K0  4224         // 512*20  = 10240
#define OFF_K1  14464        // ends 24704
#define OFF_SS  0            // 32*260  = 8320 (overlay)
#define OFF_V0  8320         // 256*36  = 9216
#define OFF_V1  17536        // ends 26752
#define OFF_RD  26752        // 512 floats
#define ATT_WORDS 27264      // 109056 B

__global__ __launch_bounds__(256, 2) void attn_kernel(float* __restrict__ out)
{
    extern __shared__ uint32_t smu[];
    uint32_t* sQ = smu + OFF_SQ;
    uint32_t* sS = smu + OFF_SS;
    float* sRedM = (float*)(smu + OFF_RD);
    float* sRedS = (float*)(smu + OFF_RD + 256);

    const uint32_t smb = (uint32_t)__cvta_generic_to_shared(smu);
    const uint32_t bK[2] = { smb + OFF_K0 * 4u, smb + OFF_K1 * 4u };
    const uint32_t bV[2] = { smb + OFF_V0 * 4u, smb + OFF_V1 * 4u };

    const int bc = blockIdx.y;
    const int q0 = blockIdx.x * 32;
    const uint32_t* Qw = g_q + (size_t)bc * S_ * EW;
    const uint32_t* Kw = g_k + (size_t)bc * S_ * EW;
    const uint32_t* Vw = g_v + (size_t)bc * E_ * SP_;
    float*          O  = out + (size_t)bc * S_ * E_;

    const int t    = threadIdx.x;
    const int warp = t >> 5;
    const int lane = t & 31;
    const int g = lane >> 2;
    const int q = lane & 3;

    // ldmatrix lane offsets
    const int arow  = (lane & 7) + (((lane >> 3) & 1) << 3);   // A pattern
    const int akadd = (lane >> 4) << 2;
    const int brow  = (lane & 7) + ((lane >> 4) << 3);         // B pattern
    const int bkadd = ((lane >> 3) & 1) << 2;

    const uint32_t aQbase = smb + (uint32_t)(OFF_SQ + arow * PQF + akadd) * 4u;
    const uint32_t aSbase = smb + (uint32_t)(OFF_SS + arow * SPP + akadd) * 4u;
    const uint32_t bKoff  = (uint32_t)(brow * PKC + bkadd) * 4u;
    const uint32_t bVoff  = (uint32_t)(brow * PVT + bkadd) * 4u;

    // ---- stage whole Q tile (32 x 128 words) ------------------------------
    #pragma unroll
    for (int i = 0; i < 4; i++) {
        const int o = t + 256 * i;
        const int row = o >> 5, j = o & 31;
        *(uint4*)&sQ[row * PQF + j * 4] =
            *(const uint4*)&Qw[(size_t)(q0 + row) * EW + j * 4];
    }

    // ---- issue K chunk 0 --------------------------------------------------
    {
        #pragma unroll
        for (int i = 0; i < 8; i++) {
            const int o = t + 256 * i;
            const int s = o >> 2, jj = o & 3;
            cpa16(bK[0] + (uint32_t)(s * PKC + jj * 4) * 4u,
                  Kw + (size_t)s * EW + jj * 4);
        }
        CP_COMMIT();
    }

    // ---------------- Phase 1: scores = Q K^T ------------------------------
    float acc[2][8][4];
    #pragma unroll
    for (int mt = 0; mt < 2; mt++)
        #pragma unroll
        for (int nt = 0; nt < 8; nt++)
            #pragma unroll
            for (int r = 0; r < 4; r++) acc[mt][nt][r] = 0.0f;

    #pragma unroll 1
    for (int cch = 0; cch < 8; cch++) {
        CP_WAIT0();
        __syncthreads();
        if (cch < 7) {
            const uint32_t dst = bK[(cch + 1) & 1];
            const int ecp = (cch + 1) * 16;
            #pragma unroll
            for (int i = 0; i < 8; i++) {
                const int o = t + 256 * i;
                const int s = o >> 2, jj = o & 3;
                cpa16(dst + (uint32_t)(s * PKC + jj * 4) * 4u,
                      Kw + (size_t)s * EW + ecp + jj * 4);
            }
            CP_COMMIT();
        }
        const uint32_t bufK = bK[cch & 1];
        const int ecp = cch * 16;
        #pragma unroll
        for (int kkp = 0; kkp < 16; kkp += 8) {
            uint32_t a[2][4], b[8][2];
            #pragma unroll
            for (int mt = 0; mt < 2; mt++)
                ldsm4(a[mt], aQbase + (uint32_t)(mt * 16 * PQF + ecp + kkp) * 4u);
            #pragma unroll
            for (int nt2 = 0; nt2 < 8; nt2 += 2) {
                uint32_t r[4];
                ldsm4(r, bufK + (uint32_t)((warp * 64 + nt2 * 8) * PKC + kkp) * 4u + bKoff);
                b[nt2][0] = r[0]; b[nt2][1] = r[1];
                b[nt2 + 1][0] = r[2]; b[nt2 + 1][1] = r[3];
            }
            #pragma unroll
            for (int mt = 0; mt < 2; mt++)
                #pragma unroll
                for (int nt = 0; nt < 8; nt++)
                    mma16(acc[mt][nt], a[mt], b[nt]);
        }
    }

    // ---------------- Softmax (fp32 on fragments) --------------------------
    float rmax[4], rinv[4];
    #pragma unroll
    for (int mt = 0; mt < 2; mt++)
        #pragma unroll
        for (int h = 0; h < 2; h++) {
            float m = -1e30f;
            #pragma unroll
            for (int nt = 0; nt < 8; nt++) {
                m = fmaxf(m, acc[mt][nt][2 * h]);
                m = fmaxf(m, acc[mt][nt][2 * h + 1]);
            }
            m = fmaxf(m, __shfl_xor_sync(0xFFFFFFFFu, m, 1));
            m = fmaxf(m, __shfl_xor_sync(0xFFFFFFFFu, m, 2));
            rmax[mt * 2 + h] = m;
        }
    __syncthreads();   // all phase-1 smem reads done

    // issue V chunk 0 ([f=256][16 pairs... 32 words? -> 32 pairs]) overlaps softmax
    {
        #pragma unroll
        for (int i = 0; i < 8; i++) {
            const int o = t + 256 * i;
            const int f = o >> 3, jj = o & 7;
            cpa16(bV[0] + (uint32_t)(f * PVT + jj * 4) * 4u,
                  Vw + (size_t)f * SP_ + jj * 4);
        }
        CP_COMMIT();
    }

    if (q == 0) {
        #pragma unroll
        for (int mt = 0; mt < 2; mt++)
            #pragma unroll
            for (int h = 0; h < 2; h++)
                sRedM[(mt * 16 + h * 8 + g) * 8 + warp] = rmax[mt * 2 + h];
    }
    __syncthreads();
    #pragma unroll
    for (int s = 0; s < 4; s++) {
        const int row = (s >> 1) * 16 + (s & 1) * 8 + g;
        float m = sRedM[row * 8];
        #pragma unroll
        for (int w = 1; w < 8; w++) m = fmaxf(m, sRedM[row * 8 + w]);
        rmax[s] = m;
    }

    #pragma unroll
    for (int mt = 0; mt < 2; mt++)
        #pragma unroll
        for (int h = 0; h < 2; h++) {
            float s = 0.0f;
            #pragma unroll
            for (int nt = 0; nt < 8; nt++) {
                float p0 = __expf(acc[mt][nt][2 * h]     - rmax[mt * 2 + h]);
                float p1 = __expf(acc[mt][nt][2 * h + 1] - rmax[mt * 2 + h]);
                acc[mt][nt][2 * h]     = p0;
                acc[mt][nt][2 * h + 1] = p1;
                s += p0 + p1;
            }
            s += __shfl_xor_sync(0xFFFFFFFFu, s, 1);
            s += __shfl_xor_sync(0xFFFFFFFFu, s, 2);
            if (q == 0) sRedS[(mt * 16 + h * 8 + g) * 8 + warp] = s;
        }
    __syncthreads();
    #pragma unroll
    for (int s = 0; s < 4; s++) {
        const int row = (s >> 1) * 16 + (s & 1) * 8 + g;
        float sum = 0.0f;
        #pragma unroll
        for (int w = 0; w < 8; w++) sum += sRedS[row * 8 + w];
        rinv[s] = 1.0f / sum;
    }

    // Store unnormalized P (bf16 pairs) to sS
    #pragma unroll
    for (int mt = 0; mt < 2; mt++)
        #pragma unroll
        for (int h = 0; h < 2; h++) {
            const int row = mt * 16 + h * 8 + g;
            #pragma unroll
            for (int nt = 0; nt < 8; nt++)
                sS[row * SPP + warp * 32 + nt * 4 + q] =
                    pk2(acc[mt][nt][2 * h], acc[mt][nt][2 * h + 1]);
        }

    // ---------------- Phase 2: out = P V -----------------------------------
    float acc2[2][4][4];
    #pragma unroll
    for (int mt = 0; mt < 2; mt++)
        #pragma unroll
        for (int nt = 0; nt < 4; nt++)
            #pragma unroll
            for (int r = 0; r < 4; r++) acc2[mt][nt][r] = 0.0f;

    #pragma unroll 1
    for (int cch = 0; cch < 8; cch++) {
        CP_WAIT0();
        __syncthreads();           // V chunk ready + (first iter) P visible
        if (cch < 7) {
            const uint32_t dst = bV[(cch + 1) & 1];
            const int spb = (cch + 1) * 32;
            #pragma unroll
            for (int i = 0; i < 8; i++) {
                const int o = t + 256 * i;
                const int f = o >> 3, jj = o & 7;
                cpa16(dst + (uint32_t)(f * PVT + jj * 4) * 4u,
                      Vw + (size_t)f * SP_ + spb + jj * 4);
            }
            CP_COMMIT();
        }
        const uint32_t bufV = bV[cch & 1];
        const int ktp = cch * 32;
        #pragma unroll
        for (int kkp = 0; kkp < 32; kkp += 8) {
            uint32_t a[2][4], b[4][2];
            #pragma unroll
            for (int mt = 0; mt < 2; mt++)
                ldsm4(a[mt], aSbase + (uint32_t)(mt * 16 * SPP + ktp + kkp) * 4u);
            #pragma unroll
            for (int nt2 = 0; nt2 < 4; nt2 += 2) {
                uint32_t r[4];
                ldsm4(r, bufV + (uint32_t)((warp * 32 + nt2 * 8) * PVT + kkp) * 4u + bVoff);
                b[nt2][0] = r[0]; b[nt2][1] = r[1];
                b[nt2 + 1][0] = r[2]; b[nt2 + 1][1] = r[3];
            }
            #pragma unroll
            for (int mt = 0; mt < 2; mt++)
                #pragma unroll
                for (int nt = 0; nt < 4; nt++)
                    mma16(acc2[mt][nt], a[mt], b[nt]);
        }
    }

    // Epilogue: normalize + store fp32
    #pragma unroll
    for (int mt = 0; mt < 2; mt++)
        #pragma unroll
        for (int h = 0; h < 2; h++) {
            const int row = q0 + mt * 16 + h * 8 + g;
            const float inv = rinv[mt * 2 + h];
            #pragma unroll
            for (int nt = 0; nt < 4; nt++) {
                const int col = warp * 32 + nt * 8 + 2 * q;
                float2 v;
                v.x = acc2[mt][nt][2 * h]     * inv;
                v.y = acc2[mt][nt][2 * h + 1] * inv;
                *(float2*)&O[(size_t)row * E_ + col] = v;
            }
        }
}

// ---------------------------------------------------------------------------
extern "C" void kernel_launch(void* const* d_in, const int* in_sizes, int n_in,
                              void* d_out, int out_size)
{
    const float* query = (const float*)d_in[0];
    const float* key   = (const float*)d_in[1];
    const float* value = (const float*)d_in[2];
    const float* wq    = (const float*)d_in[3];
    const float* wk    = (const float*)d_in[4];
    const float* wv    = (const float*)d_in[5];
    const float* bq    = (const float*)d_in[6];
    const float* bk    = (const float*)d_in[7];
    const float* bv    = (const float*)d_in[8];
    float* out = (float*)d_out;

    const float qscale = 1.0f / sqrtf((float)E_);

    dim3 pgrid(S_ / 128, E_ / 128, 3 * BC_);
    proj_kernel<<<pgrid, 256>>>(query, key, value, wq, wk, wv, bq, bk, bv, qscale);

    const size_t smem = (size_t)ATT_WORDS * sizeof(uint32_t);
    cudaFuncSetAttribute(attn_kernel, cudaFuncAttributeMaxDynamicSharedMemorySize,
                         (int)smem);
    attn_kernel<<<dim3(S_ / 32, BC_), 256, smem>>>(out);
}

// round 9
// speedup vs baseline: 12.4257x; 1.0583x over previous
#include <cuda_runtime.h>
#include <math.h>
#include <stdint.h>

#define B_ 8
#define C_ 16
#define S_ 512
#define E_ 256
#define BC_ 128
#define EW  128   // bf16x2 words per row (E/2)
#define SP_ 256   // s-pairs (S/2)

// bf16 scratch: q/k as [s][e-pair]; v TRANSPOSED: [f][s-pair]
__device__ uint32_t g_q[(size_t)BC_ * S_ * EW];
__device__ uint32_t g_k[(size_t)BC_ * S_ * EW];
__device__ uint32_t g_v[(size_t)BC_ * E_ * SP_];

// ---------------------------------------------------------------------------
// helpers
// ---------------------------------------------------------------------------
__device__ __forceinline__ uint32_t pk2(float lo, float hi) {
    uint32_t r;
    asm("cvt.rn.bf16x2.f32 %0, %1, %2;" : "=r"(r) : "f"(hi), "f"(lo));
    return r;
}
__device__ __forceinline__ uint2 pk4(float4 v) {
    uint2 u; u.x = pk2(v.x, v.y); u.y = pk2(v.z, v.w); return u;
}
__device__ __forceinline__ void mma16(float* c, const uint32_t* a, const uint32_t* b) {
    asm volatile(
        "mma.sync.aligned.m16n8k16.row.col.f32.bf16.bf16.f32 "
        "{%0,%1,%2,%3}, {%4,%5,%6,%7}, {%8,%9}, {%0,%1,%2,%3};"
        : "+f"(c[0]), "+f"(c[1]), "+f"(c[2]), "+f"(c[3])
        : "r"(a[0]), "r"(a[1]), "r"(a[2]), "r"(a[3]), "r"(b[0]), "r"(b[1]));
}
__device__ __forceinline__ void ldsm4(uint32_t* r, uint32_t addr) {
    asm volatile("ldmatrix.sync.aligned.m8n8.x4.shared.b16 {%0,%1,%2,%3}, [%4];"
                 : "=r"(r[0]), "=r"(r[1]), "=r"(r[2]), "=r"(r[3]) : "r"(addr));
}
__device__ __forceinline__ void cpa16(uint32_t smem_addr, const void* gptr) {
    asm volatile("cp.async.cg.shared.global [%0], [%1], 16;"
                 :: "r"(smem_addr), "l"(gptr));
}
#define CP_COMMIT() asm volatile("cp.async.commit_group;")
#define CP_WAIT0()  asm volatile("cp.async.wait_group 0;")
#define CP_WAIT1()  asm volatile("cp.async.wait_group 1;")

// ---------------------------------------------------------------------------
// Projection (merged q/k/v) — unchanged from R8 (verified).
// ---------------------------------------------------------------------------
#define PA  36
#define PBP 136
#define PT  68

__global__ __launch_bounds__(256) void proj_kernel(
    const float* __restrict__ query, const float* __restrict__ key,
    const float* __restrict__ value,
    const float* __restrict__ wq, const float* __restrict__ wk,
    const float* __restrict__ wv,
    const float* __restrict__ bq, const float* __restrict__ bk,
    const float* __restrict__ bv, float qscale)
{
    __shared__ uint32_t pool[8960];
    uint32_t* sA = pool;
    uint32_t* sB = pool + 4608;
    uint32_t* sT = pool;

    const int zi    = blockIdx.z;
    const int which = zi >> 7;
    const int bc    = zi & (BC_ - 1);
    const int c     = bc % C_;

    const float *X, *W, *bp;
    uint32_t* Yw;
    float scale;
    if (which == 0)      { X = query; W = wq; bp = bq; Yw = g_q + (size_t)bc * S_ * EW; scale = qscale; }
    else if (which == 1) { X = key;   W = wk; bp = bk; Yw = g_k + (size_t)bc * S_ * EW; scale = 1.0f; }
    else                 { X = value; W = wv; bp = bv; Yw = g_v + (size_t)bc * E_ * SP_; scale = 1.0f; }
    X  += (size_t)bc * S_ * E_;
    W  += (size_t)c  * E_ * E_;
    bp += (size_t)c  * E_;

    const int m0 = blockIdx.x * 128;
    const int n0 = blockIdx.y * 128;
    const int t  = threadIdx.x;
    const int warp  = t >> 5;
    const int warpm = warp >> 2;
    const int warpn = warp & 3;
    const int lane  = t & 31;
    const int g = lane >> 2;
    const int q = lane & 3;

    const int arow  = (lane & 7) + (((lane >> 3) & 1) << 3);
    const int akadd = (lane >> 4) << 2;
    const uint32_t smbA = (uint32_t)__cvta_generic_to_shared(sA);
    const uint32_t aBase = smbA + (uint32_t)(arow * PA + akadd) * 4u;

    float acc[4][4][4];
    #pragma unroll
    for (int i = 0; i < 4; i++)
        #pragma unroll
        for (int j = 0; j < 4; j++)
            #pragma unroll
            for (int r = 0; r < 4; r++) acc[i][j][r] = 0.0f;

    for (int k0 = 0; k0 < E_; k0 += 64) {
        #pragma unroll
        for (int i = 0; i < 8; i++) {
            const int idx = t + 256 * i;
            const int row = idx >> 4, c4 = idx & 15;
            *(uint2*)&sA[row * PA + c4 * 2] =
                pk4(*(const float4*)&X[(size_t)(m0 + row) * E_ + k0 + 4 * c4]);
        }
        #pragma unroll
        for (int i = 0; i < 4; i++) {
            const int idx = t + 256 * i;
            const int kp = idx >> 5, n4 = (idx & 31) * 4;
            const float4 w0 = *(const float4*)&W[(size_t)(k0 + 2 * kp)     * E_ + n0 + n4];
            const float4 w1 = *(const float4*)&W[(size_t)(k0 + 2 * kp + 1) * E_ + n0 + n4];
            uint4 u;
            u.x = pk2(w0.x, w1.x); u.y = pk2(w0.y, w1.y);
            u.z = pk2(w0.z, w1.z); u.w = pk2(w0.w, w1.w);
            *(uint4*)&sB[kp * PBP + n4] = u;
        }
        __syncthreads();

        #pragma unroll
        for (int kkp = 0; kkp < 32; kkp += 8) {
            uint32_t a[4][4], b[4][2];
            #pragma unroll
            for (int mt = 0; mt < 4; mt++)
                ldsm4(a[mt], aBase + (uint32_t)((warpm * 64 + mt * 16) * PA + kkp) * 4u);
            #pragma unroll
            for (int nt = 0; nt < 4; nt++) {
                const int n = warpn * 32 + nt * 8 + g;
                b[nt][0] = sB[(kkp + q) * PBP + n];
                b[nt][1] = sB[(kkp + q + 4) * PBP + n];
            }
            #pragma unroll
            for (int mt = 0; mt < 4; mt++)
                #pragma unroll
                for (int nt = 0; nt < 4; nt++)
                    mma16(acc[mt][nt], a[mt], b[nt]);
        }
        __syncthreads();
    }

    if (which != 2) {
        #pragma unroll
        for (int nt = 0; nt < 4; nt++) {
            const int col = n0 + warpn * 32 + nt * 8 + 2 * q;
            const float b0v = bp[col], b1v = bp[col + 1];
            #pragma unroll
            for (int mt = 0; mt < 4; mt++) {
                const int row = m0 + warpm * 64 + mt * 16 + g;
                const float v00 = fmaxf(acc[mt][nt][0] + b0v, 0.0f) * scale;
                const float v01 = fmaxf(acc[mt][nt][1] + b1v, 0.0f) * scale;
                const float v10 = fmaxf(acc[mt][nt][2] + b0v, 0.0f) * scale;
                const float v11 = fmaxf(acc[mt][nt][3] + b1v, 0.0f) * scale;
                const int cw = (n0 >> 1) + warpn * 16 + nt * 4 + q;
                Yw[(size_t)row * EW + cw]       = pk2(v00, v01);
                Yw[(size_t)(row + 8) * EW + cw] = pk2(v10, v11);
            }
        }
    } else {
        #pragma unroll
        for (int nt = 0; nt < 4; nt++) {
            const int col = n0 + warpn * 32 + nt * 8 + 2 * q;
            const float b0v = bp[col], b1v = bp[col + 1];
            #pragma unroll
            for (int mt = 0; mt < 4; mt++) {
                const float v00 = fmaxf(acc[mt][nt][0] + b0v, 0.0f);
                const float v01 = fmaxf(acc[mt][nt][1] + b1v, 0.0f);
                const float v10 = fmaxf(acc[mt][nt][2] + b0v, 0.0f);
                const float v11 = fmaxf(acc[mt][nt][3] + b1v, 0.0f);
                const float p00 = __shfl_xor_sync(0xFFFFFFFFu, v00, 4);
                const float p01 = __shfl_xor_sync(0xFFFFFFFFu, v01, 4);
                const float p10 = __shfl_xor_sync(0xFFFFFFFFu, v10, 4);
                const float p11 = __shfl_xor_sync(0xFFFFFFFFu, v11, 4);
                if ((g & 1) == 0) {
                    const int lcol = warpn * 32 + nt * 8 + 2 * q;
                    const int lsp  = (warpm * 64 + mt * 16 + g) >> 1;
                    sT[lcol * PT + lsp]           = pk2(v00, p00);
                    sT[(lcol + 1) * PT + lsp]     = pk2(v01, p01);
                    sT[lcol * PT + lsp + 4]       = pk2(v10, p10);
                    sT[(lcol + 1) * PT + lsp + 4] = pk2(v11, p11);
                }
            }
        }
        __syncthreads();
        const int spb = m0 >> 1;
        #pragma unroll
        for (int i = 0; i < 8; i++) {
            const int o = t + 256 * i;
            const int col = o >> 4, j = o & 15;
            *(uint4*)&Yw[(size_t)(n0 + col) * SP_ + spb + j * 4] =
                *(uint4*)&sT[col * PT + j * 4];
        }
    }
}

// ---------------------------------------------------------------------------
// Attention v4: 64 q-rows/CTA, 512 threads (16 warps, 2m x 8n), scores in
// registers, 3-stage cp.async pipeline, ldmatrix operands.
// ---------------------------------------------------------------------------
#define PQF 132
#define PKC 20
#define SPP 260
#define PVT 36

#define OFF_SQ 0             // 64*132 = 8448
#define OFF_K  8448          // 3 x 10240 -> ends 39168
#define KSTR   10240
#define OFF_SS 0             // 64*260 = 16640 (overlay)
#define OFF_V  16640         // 3 x 9216 -> ends 44288
#define VSTR   9216
#define OFF_RD 44288         // 1024 floats
#define ATT_WORDS 45312      // 181248 B

__global__ __launch_bounds__(512, 1) void attn_kernel(float* __restrict__ out)
{
    extern __shared__ uint32_t smu[];
    uint32_t* sQ = smu + OFF_SQ;
    uint32_t* sS = smu + OFF_SS;
    float* sRedM = (float*)(smu + OFF_RD);         // [64 rows][8 wn]
    float* sRedS = (float*)(smu + OFF_RD + 512);

    const uint32_t smb = (uint32_t)__cvta_generic_to_shared(smu);

    const int bc = blockIdx.y;
    const int q0 = blockIdx.x * 64;
    const uint32_t* Qw = g_q + (size_t)bc * S_ * EW;
    const uint32_t* Kw = g_k + (size_t)bc * S_ * EW;
    const uint32_t* Vw = g_v + (size_t)bc * E_ * SP_;
    float*          O  = out + (size_t)bc * S_ * E_;

    const int t    = threadIdx.x;
    const int warp = t >> 5;
    const int wm   = warp >> 3;    // 0..1
    const int wn   = warp & 7;     // 0..7
    const int lane = t & 31;
    const int g = lane >> 2;
    const int q = lane & 3;

    // ldmatrix lane offsets
    const int arow  = (lane & 7) + (((lane >> 3) & 1) << 3);
    const int akadd = (lane >> 4) << 2;
    const int brow  = (lane & 7) + ((lane >> 4) << 3);
    const int bkadd = ((lane >> 3) & 1) << 2;

    const uint32_t aQbase = smb + (uint32_t)(OFF_SQ + (wm * 32 + arow) * PQF + akadd) * 4u;
    const uint32_t aSbase = smb + (uint32_t)(OFF_SS + (wm * 32 + arow) * SPP + akadd) * 4u;
    const uint32_t bKoff  = (uint32_t)(brow * PKC + bkadd) * 4u;
    const uint32_t bVoff  = (uint32_t)(brow * PVT + bkadd) * 4u;

    // ---- issue K chunks 0,1 (3-stage prologue) ---------------------------
    #pragma unroll
    for (int pc = 0; pc < 2; pc++) {
        const uint32_t dst = smb + (uint32_t)(OFF_K + pc * KSTR) * 4u;
        const int ecp = pc * 16;
        #pragma unroll
        for (int i = 0; i < 4; i++) {
            const int o = t + 512 * i;
            const int s = o >> 2, jj = o & 3;
            cpa16(dst + (uint32_t)(s * PKC + jj * 4) * 4u,
                  Kw + (size_t)s * EW + ecp + jj * 4);
        }
        CP_COMMIT();
    }

    // ---- stage whole Q tile (64 x 128 words) -----------------------------
    #pragma unroll
    for (int i = 0; i < 4; i++) {
        const int o = t + 512 * i;
        const int row = o >> 5, j = o & 31;
        *(uint4*)&sQ[row * PQF + j * 4] =
            *(const uint4*)&Qw[(size_t)(q0 + row) * EW + j * 4];
    }

    // ---------------- Phase 1: scores = Q K^T ------------------------------
    float acc[2][8][4];
    #pragma unroll
    for (int mt = 0; mt < 2; mt++)
        #pragma unroll
        for (int nt = 0; nt < 8; nt++)
            #pragma unroll
            for (int r = 0; r < 4; r++) acc[mt][nt][r] = 0.0f;

    #pragma unroll 1
    for (int cch = 0; cch < 8; cch++) {
        if (cch >= 6) { CP_WAIT0(); } else { CP_WAIT1(); }
        __syncthreads();
        if (cch < 6) {
            const uint32_t dst = smb + (uint32_t)(OFF_K + ((cch + 2) % 3) * KSTR) * 4u;
            const int ecp = (cch + 2) * 16;
            #pragma unroll
            for (int i = 0; i < 4; i++) {
                const int o = t + 512 * i;
                const int s = o >> 2, jj = o & 3;
                cpa16(dst + (uint32_t)(s * PKC + jj * 4) * 4u,
                      Kw + (size_t)s * EW + ecp + jj * 4);
            }
            CP_COMMIT();
        }
        const uint32_t bufK = smb + (uint32_t)(OFF_K + (cch % 3) * KSTR) * 4u;
        const int ecp = cch * 16;
        #pragma unroll
        for (int kkp = 0; kkp < 16; kkp += 8) {
            uint32_t a[2][4], b[8][2];
            #pragma unroll
            for (int mt = 0; mt < 2; mt++)
                ldsm4(a[mt], aQbase + (uint32_t)(mt * 16 * PQF + ecp + kkp) * 4u);
            #pragma unroll
            for (int nt2 = 0; nt2 < 8; nt2 += 2) {
                uint32_t r[4];
                ldsm4(r, bufK + (uint32_t)((wn * 64 + nt2 * 8) * PKC + kkp) * 4u + bKoff);
                b[nt2][0] = r[0]; b[nt2][1] = r[1];
                b[nt2 + 1][0] = r[2]; b[nt2 + 1][1] = r[3];
            }
            #pragma unroll
            for (int mt = 0; mt < 2; mt++)
                #pragma unroll
                for (int nt = 0; nt < 8; nt++)
                    mma16(acc[mt][nt], a[mt], b[nt]);
        }
    }

    // ---------------- Softmax (fp32 on fragments) --------------------------
    float rmax[4], rinv[4];
    #pragma unroll
    for (int mt = 0; mt < 2; mt++)
        #pragma unroll
        for (int h = 0; h < 2; h++) {
            float m = -1e30f;
            #pragma unroll
            for (int nt = 0; nt < 8; nt++) {
                m = fmaxf(m, acc[mt][nt][2 * h]);
                m = fmaxf(m, acc[mt][nt][2 * h + 1]);
            }
            m = fmaxf(m, __shfl_xor_sync(0xFFFFFFFFu, m, 1));
            m = fmaxf(m, __shfl_xor_sync(0xFFFFFFFFu, m, 2));
            rmax[mt * 2 + h] = m;
        }
    __syncthreads();   // all phase-1 K/Q smem reads done — overlays now safe

    // ---- issue V chunks 0,1 (overlaps the whole softmax) ------------------
    #pragma unroll
    for (int pc = 0; pc < 2; pc++) {
        const uint32_t dst = smb + (uint32_t)(OFF_V + pc * VSTR) * 4u;
        const int spb = pc * 32;
        #pragma unroll
        for (int i = 0; i < 4; i++) {
            const int o = t + 512 * i;
            const int f = o >> 3, jj = o & 7;
            cpa16(dst + (uint32_t)(f * PVT + jj * 4) * 4u,
                  Vw + (size_t)f * SP_ + spb + jj * 4);
        }
        CP_COMMIT();
    }

    if (q == 0) {
        #pragma unroll
        for (int mt = 0; mt < 2; mt++)
            #pragma unroll
            for (int h = 0; h < 2; h++)
                sRedM[(wm * 32 + mt * 16 + h * 8 + g) * 8 + wn] = rmax[mt * 2 + h];
    }
    __syncthreads();
    #pragma unroll
    for (int s = 0; s < 4; s++) {
        const int row = wm * 32 + (s >> 1) * 16 + (s & 1) * 8 + g;
        float m = sRedM[row * 8];
        #pragma unroll
        for (int w = 1; w < 8; w++) m = fmaxf(m, sRedM[row * 8 + w]);
        rmax[s] = m;
    }

    #pragma unroll
    for (int mt = 0; mt < 2; mt++)
        #pragma unroll
        for (int h = 0; h < 2; h++) {
            float s = 0.0f;
            #pragma unroll
            for (int nt = 0; nt < 8; nt++) {
                float p0 = __expf(acc[mt][nt][2 * h]     - rmax[mt * 2 + h]);
                float p1 = __expf(acc[mt][nt][2 * h + 1] - rmax[mt * 2 + h]);
                acc[mt][nt][2 * h]     = p0;
                acc[mt][nt][2 * h + 1] = p1;
                s += p0 + p1;
            }
            s += __shfl_xor_sync(0xFFFFFFFFu, s, 1);
            s += __shfl_xor_sync(0xFFFFFFFFu, s, 2);
            if (q == 0) sRedS[(wm * 32 + mt * 16 + h * 8 + g) * 8 + wn] = s;
        }
    __syncthreads();
    #pragma unroll
    for (int s = 0; s < 4; s++) {
        const int row = wm * 32 + (s >> 1) * 16 + (s & 1) * 8 + g;
        float sum = 0.0f;
        #pragma unroll
        for (int w = 0; w < 8; w++) sum += sRedS[row * 8 + w];
        rinv[s] = 1.0f / sum;
    }

    // Store unnormalized P (bf16 pairs) to sS
    #pragma unroll
    for (int mt = 0; mt < 2; mt++)
        #pragma unroll
        for (int h = 0; h < 2; h++) {
            const int row = wm * 32 + mt * 16 + h * 8 + g;
            #pragma unroll
            for (int nt = 0; nt < 8; nt++)
                sS[row * SPP + wn * 32 + nt * 4 + q] =
                    pk2(acc[mt][nt][2 * h], acc[mt][nt][2 * h + 1]);
        }

    // ---------------- Phase 2: out = P V -----------------------------------
    float acc2[2][4][4];
    #pragma unroll
    for (int mt = 0; mt < 2; mt++)
        #pragma unroll
        for (int nt = 0; nt < 4; nt++)
            #pragma unroll
            for (int r = 0; r < 4; r++) acc2[mt][nt][r] = 0.0f;

    #pragma unroll 1
    for (int cch = 0; cch < 8; cch++) {
        if (cch >= 6) { CP_WAIT0(); } else { CP_WAIT1(); }
        __syncthreads();           // V chunk ready + (first iter) P visible
        if (cch < 6) {
            const uint32_t dst = smb + (uint32_t)(OFF_V + ((cch + 2) % 3) * VSTR) * 4u;
            const int spb = (cch + 2) * 32;
            #pragma unroll
            for (int i = 0; i < 4; i++) {
                const int o = t + 512 * i;
                const int f = o >> 3, jj = o & 7;
                cpa16(dst + (uint32_t)(f * PVT + jj * 4) * 4u,
                      Vw + (size_t)f * SP_ + spb + jj * 4);
            }
            CP_COMMIT();
        }
        const uint32_t bufV = smb + (uint32_t)(OFF_V + (cch % 3) * VSTR) * 4u;
        const int ktp = cch * 32;
        #pragma unroll
        for (int kkp = 0; kkp < 32; kkp += 8) {
            uint32_t a[2][4], b[4][2];
            #pragma unroll
            for (int mt = 0; mt < 2; mt++)
                ldsm4(a[mt], aSbase + (uint32_t)(mt * 16 * SPP + ktp + kkp) * 4u);
            #pragma unroll
            for (int nt2 = 0; nt2 < 4; nt2 += 2) {
                uint32_t r[4];
                ldsm4(r, bufV + (uint32_t)((wn * 32 + nt2 * 8) * PVT + kkp) * 4u + bVoff);
                b[nt2][0] = r[0]; b[nt2][1] = r[1];
                b[nt2 + 1][0] = r[2]; b[nt2 + 1][1] = r[3];
            }
            #pragma unroll
            for (int mt = 0; mt < 2; mt++)
                #pragma unroll
                for (int nt = 0; nt < 4; nt++)
                    mma16(acc2[mt][nt], a[mt], b[nt]);
        }
    }

    // Epilogue: normalize + store fp32
    #pragma unroll
    for (int mt = 0; mt < 2; mt++)
        #pragma unroll
        for (int h = 0; h < 2; h++) {
            const int row = q0 + wm * 32 + mt * 16 + h * 8 + g;
            const float inv = rinv[mt * 2 + h];
            #pragma unroll
            for (int nt = 0; nt < 4; nt++) {
                const int col = wn * 32 + nt * 8 + 2 * q;
                float2 v;
                v.x = acc2[mt][nt][2 * h]     * inv;
                v.y = acc2[mt][nt][2 * h + 1] * inv;
                *(float2*)&O[(size_t)row * E_ + col] = v;
            }
        }
}

// ---------------------------------------------------------------------------
extern "C" void kernel_launch(void* const* d_in, const int* in_sizes, int n_in,
                              void* d_out, int out_size)
{
    const float* query = (const float*)d_in[0];
    const float* key   = (const float*)d_in[1];
    const float* value = (const float*)d_in[2];
    const float* wq    = (const float*)d_in[3];
    const float* wk    = (const float*)d_in[4];
    const float* wv    = (const float*)d_in[5];
    const float* bq    = (const float*)d_in[6];
    const float* bk    = (const float*)d_in[7];
    const float* bv    = (const float*)d_in[8];
    float* out = (float*)d_out;

    const float qscale = 1.0f / sqrtf((float)E_);

    dim3 pgrid(S_ / 128, E_ / 128, 3 * BC_);
    proj_kernel<<<pgrid, 256>>>(query, key, value, wq, wk, wv, bq, bk, bv, qscale);

    const size_t smem = (size_t)ATT_WORDS * sizeof(uint32_t);
    cudaFuncSetAttribute(attn_kernel, cudaFuncAttributeMaxDynamicSharedMemorySize,
                         (int)smem);
    attn_kernel<<<dim3(S_ / 64, BC_), 512, smem>>>(out);
}